// round 9
// baseline (speedup 1.0000x reference)
#include <cuda_runtime.h>
#include <math.h>
#include <stdint.h>

#define BB 256
#define SS 512
#define DD 256
#define HH 256
#define OO 128
#define NCOL 1024            // 4 gates * HH
#define ROWS_PER_CTA 16
#define JS 32                // hidden-j slice per scan CTA
#define CLS 128              // 4 gates * JS (interleaved [k][jj*4+g])
#define CLUSTER 8
// Ws + double-buffered hs (floats) + exchange buffer (1024 ull)
#define SCAN_SMEM ((HH*CLS + 2*ROWS_PER_CTA*HH) * 4 + 1024 * 8)

// ---------- device scratch (static; no runtime allocation) ----------
__device__ float g_XP[(size_t)SS * BB * NCOL];   // [s][b][n], n = gate*256 + j
__device__ float g_Hfin[BB * HH];                // final hidden state

struct P1Params {
    const float* x;
    const float* Wx[4];
    const float* Wxb[4];
    const float* Whb[4];
    const float* bgate[4];
};
struct ScanParams { const float* Wh[4]; };

// ---------- packed f32x2 helpers (Blackwell FFMA2) ----------
__device__ __forceinline__ unsigned long long pack2(float lo, float hi) {
    unsigned long long r;
    asm("mov.b64 %0, {%1, %2};"
        : "=l"(r) : "r"(__float_as_uint(lo)), "r"(__float_as_uint(hi)));
    return r;
}
__device__ __forceinline__ void fma2(unsigned long long& d,
                                     unsigned long long a, unsigned long long b) {
    asm("fma.rn.f32x2 %0, %1, %2, %0;" : "+l"(d) : "l"(a), "l"(b));
}
__device__ __forceinline__ void add2(unsigned long long& d, unsigned long long a) {
    asm("add.rn.f32x2 %0, %0, %1;" : "+l"(d) : "l"(a));
}
__device__ __forceinline__ float2 unpack2(unsigned long long v) {
    unsigned lo, hi;
    asm("mov.b64 {%0, %1}, %2;" : "=r"(lo), "=r"(hi) : "l"(v));
    return make_float2(__uint_as_float(lo), __uint_as_float(hi));
}
__device__ __forceinline__ uint32_t s2u(const void* p) {
    uint32_t a;
    asm("{ .reg .u64 t; cvta.to.shared.u64 t, %1; cvt.u32.u64 %0, t; }"
        : "=r"(a) : "l"(p));
    return a;
}
__device__ __forceinline__ void st_cluster_u64(uint32_t laddr, int rank,
                                               unsigned long long v) {
    uint32_t raddr;
    asm("mapa.shared::cluster.u32 %0, %1, %2;" : "=r"(raddr) : "r"(laddr), "r"(rank));
    asm volatile("st.shared::cluster.b64 [%0], %1;" :: "r"(raddr), "l"(v) : "memory");
}

// ---------- phase 1: XP = x @ Wx^T + (Wx_b + Wh_b) + bgate ----------
// M=131072, N=1024, K=256. 128x128 tile, 256 thr, 8x8 per thread (FFMA2).
__global__ __launch_bounds__(256, 2) void p1_gemm(P1Params p) {
    __shared__ __align__(16) float As[16][132];
    __shared__ __align__(16) float Bs[16][132];
    const int tid = threadIdx.x;
    const int tm = tid >> 4, tn = tid & 15;
    const int ml = tid >> 2;
    const int kl = (tid & 3) * 4;
    const int g   = blockIdx.x >> 1;
    const int j0g = (blockIdx.x & 1) * 128;

    const float* Aptr0 = p.x + (size_t)(blockIdx.y * 128 + ml) * DD + kl;
    const float* Aptr1 = Aptr0 + (size_t)64 * DD;
    const float* Bptr0 = p.Wx[g] + (size_t)(j0g + ml) * DD + kl;
    const float* Bptr1 = Bptr0 + (size_t)64 * DD;

    unsigned long long acc[8][4];
#pragma unroll
    for (int r = 0; r < 8; r++)
#pragma unroll
        for (int c = 0; c < 4; c++) acc[r][c] = 0ull;

    for (int kt = 0; kt < DD; kt += 16) {
        float4 a0 = *(const float4*)(Aptr0 + kt);
        float4 a1 = *(const float4*)(Aptr1 + kt);
        float4 b0 = *(const float4*)(Bptr0 + kt);
        float4 b1 = *(const float4*)(Bptr1 + kt);
        As[kl+0][ml] = a0.x; As[kl+1][ml] = a0.y; As[kl+2][ml] = a0.z; As[kl+3][ml] = a0.w;
        As[kl+0][ml+64] = a1.x; As[kl+1][ml+64] = a1.y; As[kl+2][ml+64] = a1.z; As[kl+3][ml+64] = a1.w;
        Bs[kl+0][ml] = b0.x; Bs[kl+1][ml] = b0.y; Bs[kl+2][ml] = b0.z; Bs[kl+3][ml] = b0.w;
        Bs[kl+0][ml+64] = b1.x; Bs[kl+1][ml+64] = b1.y; Bs[kl+2][ml+64] = b1.z; Bs[kl+3][ml+64] = b1.w;
        __syncthreads();
#pragma unroll
        for (int kk = 0; kk < 16; kk++) {
            float4 av0 = *(const float4*)&As[kk][tm * 8];
            float4 av1 = *(const float4*)&As[kk][tm * 8 + 4];
            ulonglong2 bv0 = *(const ulonglong2*)&Bs[kk][tn * 8];
            ulonglong2 bv1 = *(const ulonglong2*)&Bs[kk][tn * 8 + 4];
            float ar[8] = {av0.x, av0.y, av0.z, av0.w, av1.x, av1.y, av1.z, av1.w};
#pragma unroll
            for (int r = 0; r < 8; r++) {
                unsigned long long ap = pack2(ar[r], ar[r]);
                fma2(acc[r][0], ap, bv0.x);
                fma2(acc[r][1], ap, bv0.y);
                fma2(acc[r][2], ap, bv1.x);
                fma2(acc[r][3], ap, bv1.y);
            }
        }
        __syncthreads();
    }

    const int jc = j0g + tn * 8;
    const int n0 = blockIdx.x * 128 + tn * 8;
    float4 wbl = *(const float4*)&p.Wxb[g][jc];
    float4 wbh = *(const float4*)&p.Wxb[g][jc + 4];
    float4 hbl = *(const float4*)&p.Whb[g][jc];
    float4 hbh = *(const float4*)&p.Whb[g][jc + 4];
    wbl.x += hbl.x; wbl.y += hbl.y; wbl.z += hbl.z; wbl.w += hbl.w;
    wbh.x += hbh.x; wbh.y += hbh.y; wbh.z += hbh.z; wbh.w += hbh.w;
#pragma unroll
    for (int rr = 0; rr < 8; rr++) {
        int m = blockIdx.y * 128 + tm * 8 + rr;
        int b = m >> 9;
        int s = m & 511;
        float4 bgl = *(const float4*)(p.bgate[g] + (size_t)b * HH + jc);
        float4 bgh = *(const float4*)(p.bgate[g] + (size_t)b * HH + jc + 4);
        float2 p0 = unpack2(acc[rr][0]);
        float2 p1 = unpack2(acc[rr][1]);
        float2 p2 = unpack2(acc[rr][2]);
        float2 p3 = unpack2(acc[rr][3]);
        float4 o0 = make_float4(p0.x + wbl.x + bgl.x, p0.y + wbl.y + bgl.y,
                                p1.x + wbl.z + bgl.z, p1.y + wbl.w + bgl.w);
        float4 o1 = make_float4(p2.x + wbh.x + bgh.x, p2.y + wbh.y + bgh.y,
                                p3.x + wbh.z + bgh.z, p3.y + wbh.w + bgh.w);
        float* dst = &g_XP[((size_t)s * BB + b) * NCOL + n0];
        *(float4*)dst = o0;
        *(float4*)(dst + 4) = o1;
    }
}

// ---------- persistent recurrent scan (cluster DSMEM h-exchange) ----------
// 16 clusters of 8 CTAs. Cluster = one batch-row group (16 rows); CTA rank cb
// owns j in [cb*32,+32). Ws interleaved [k][jj*4+g] resident in SMEM.
// h kept in double-buffered SMEM, exchanged via st.shared::cluster pushes +
// one barrier.cluster per step. No global h traffic until the final step.
__global__ __launch_bounds__(256, 1) __cluster_dims__(CLUSTER, 1, 1)
void scan_kernel(ScanParams p) {
    extern __shared__ __align__(16) float smem_f[];
    float* Ws = smem_f;                              // [k][c] 256*128
    float* hs = Ws + HH * CLS;                       // [2][16][256]
    unsigned long long* ex = (unsigned long long*)(hs + 2 * ROWS_PER_CTA * HH);

    const int tid = threadIdx.x;
    const int cb = blockIdx.x & 7;                   // == cluster rank
    const int rb = blockIdx.x >> 3;
    const int b0 = rb * ROWS_PER_CTA;
    const int j0 = cb * JS;

    // Ws load, gate-interleaved: Ws[k*128 + jj*4 + g] = Wh_g[j0+jj][k]
    for (int idx = tid; idx < CLS * HH; idx += 256) {
        int k = idx >> 7;
        int c = idx & 127;
        int jjx = c >> 2;
        int gx = c & 3;
        Ws[k * CLS + c] = p.Wh[gx][(size_t)(j0 + jjx) * HH + k];
    }
    // zero read buffer 0 (h0 = 0)
    for (int idx = tid; idx < ROWS_PER_CTA * HH; idx += 256) hs[idx] = 0.f;
    __syncthreads();

    const int kh = tid >> 7;            // k-half
    const int rg = (tid >> 5) & 3;      // row group (4 rows)
    const int jj = tid & 31;
    const int rbase = rg * 4;
    const int kbase = kh * 128;
    const int rown0 = rbase + 2 * kh;   // owned rows: rown0, rown0+1
    float c0v = 0.f, c1v = 0.f;         // cell state (registers)

    unsigned long long* exw = ex + (size_t)((kh * 4 + rg) * 4) * 32 + jj;
    unsigned long long* exr = ex + (size_t)(((1 - kh) * 4 + rg) * 4) * 32 + jj;
    const float* wrow = Ws + (size_t)kbase * CLS + jj * 4;

    const bool evenlane = (jj & 1) == 0;
    // store target row/col (pair layout via shfl)
    const int st_row = evenlane ? rown0 : (rown0 + 1);
    const int st_col = j0 + (evenlane ? jj : (jj - 1));

    for (int t = 0; t < SS; t++) {
        const float* hbuf = hs + (t & 1) * (ROWS_PER_CTA * HH);
        float* hnext = hs + ((t + 1) & 1) * (ROWS_PER_CTA * HH);

        // prefetch this step's xp for the two owned rows (4 gates each)
        const float* xpb = g_XP + ((size_t)t * BB + b0) * NCOL + j0 + jj;
        const float* xpr0 = xpb + (size_t)rown0 * NCOL;
        const float* xpr1 = xpr0 + NCOL;
        float xg0 = xpr0[0], xi0 = xpr0[256], xf0 = xpr0[512], xo0 = xpr0[768];
        float xg1 = xpr1[0], xi1 = xpr1[256], xf1 = xpr1[512], xo1 = xpr1[768];

        unsigned long long aGI0 = 0, aGI1 = 0, aGI2 = 0, aGI3 = 0;
        unsigned long long aFO0 = 0, aFO1 = 0, aFO2 = 0, aFO3 = 0;
        const float* h0 = hbuf + (rbase + 0) * HH + kbase;
        const float* h1 = h0 + HH;
        const float* h2 = h1 + HH;
        const float* h3 = h2 + HH;
        for (int k4 = 0; k4 < 128; k4 += 4) {
            float4 v0 = *(const float4*)&h0[k4];
            float4 v1 = *(const float4*)&h1[k4];
            float4 v2 = *(const float4*)&h2[k4];
            float4 v3 = *(const float4*)&h3[k4];
            {
                ulonglong2 wp = *(const ulonglong2*)&wrow[(size_t)(k4 + 0) * CLS];
                unsigned long long p0 = pack2(v0.x, v0.x), p1 = pack2(v1.x, v1.x);
                unsigned long long p2 = pack2(v2.x, v2.x), p3 = pack2(v3.x, v3.x);
                fma2(aGI0, p0, wp.x); fma2(aFO0, p0, wp.y);
                fma2(aGI1, p1, wp.x); fma2(aFO1, p1, wp.y);
                fma2(aGI2, p2, wp.x); fma2(aFO2, p2, wp.y);
                fma2(aGI3, p3, wp.x); fma2(aFO3, p3, wp.y);
            }
            {
                ulonglong2 wp = *(const ulonglong2*)&wrow[(size_t)(k4 + 1) * CLS];
                unsigned long long p0 = pack2(v0.y, v0.y), p1 = pack2(v1.y, v1.y);
                unsigned long long p2 = pack2(v2.y, v2.y), p3 = pack2(v3.y, v3.y);
                fma2(aGI0, p0, wp.x); fma2(aFO0, p0, wp.y);
                fma2(aGI1, p1, wp.x); fma2(aFO1, p1, wp.y);
                fma2(aGI2, p2, wp.x); fma2(aFO2, p2, wp.y);
                fma2(aGI3, p3, wp.x); fma2(aFO3, p3, wp.y);
            }
            {
                ulonglong2 wp = *(const ulonglong2*)&wrow[(size_t)(k4 + 2) * CLS];
                unsigned long long p0 = pack2(v0.z, v0.z), p1 = pack2(v1.z, v1.z);
                unsigned long long p2 = pack2(v2.z, v2.z), p3 = pack2(v3.z, v3.z);
                fma2(aGI0, p0, wp.x); fma2(aFO0, p0, wp.y);
                fma2(aGI1, p1, wp.x); fma2(aFO1, p1, wp.y);
                fma2(aGI2, p2, wp.x); fma2(aFO2, p2, wp.y);
                fma2(aGI3, p3, wp.x); fma2(aFO3, p3, wp.y);
            }
            {
                ulonglong2 wp = *(const ulonglong2*)&wrow[(size_t)(k4 + 3) * CLS];
                unsigned long long p0 = pack2(v0.w, v0.w), p1 = pack2(v1.w, v1.w);
                unsigned long long p2 = pack2(v2.w, v2.w), p3 = pack2(v3.w, v3.w);
                fma2(aGI0, p0, wp.x); fma2(aFO0, p0, wp.y);
                fma2(aGI1, p1, wp.x); fma2(aFO1, p1, wp.y);
                fma2(aGI2, p2, wp.x); fma2(aFO2, p2, wp.y);
                fma2(aGI3, p3, wp.x); fma2(aFO3, p3, wp.y);
            }
        }

        // exchange k-half partials within CTA
        unsigned long long wA = kh ? aGI0 : aGI2;
        unsigned long long wB = kh ? aFO0 : aFO2;
        unsigned long long wC = kh ? aGI1 : aGI3;
        unsigned long long wD = kh ? aFO1 : aFO3;
        unsigned long long oGI0 = kh ? aGI2 : aGI0;
        unsigned long long oFO0 = kh ? aFO2 : aFO0;
        unsigned long long oGI1 = kh ? aGI3 : aGI1;
        unsigned long long oFO1 = kh ? aFO3 : aFO1;
        exw[0] = wA; exw[32] = wB; exw[64] = wC; exw[96] = wD;
        __syncthreads();
        add2(oGI0, exr[0]);
        add2(oFO0, exr[32]);
        add2(oGI1, exr[64]);
        add2(oFO1, exr[96]);

        // gate math in-register for the 2 owned rows
        float hv0, hv1;
        {
            float2 gi = unpack2(oGI0);
            float2 fo = unpack2(oFO0);
            float pg = gi.x + xg0, pi = gi.y + xi0, pf = fo.x + xf0, po = fo.y + xo0;
            float gv = tanhf(pg);
            float iv = 1.f / (1.f + expf(-pi));
            float fv = 1.f / (1.f + expf(-pf));
            float ov = 1.f / (1.f + expf(-po));
            c0v = fmaf(gv, iv, c0v * fv);
            hv0 = tanhf(c0v) * ov;
        }
        {
            float2 gi = unpack2(oGI1);
            float2 fo = unpack2(oFO1);
            float pg = gi.x + xg1, pi = gi.y + xi1, pf = fo.x + xf1, po = fo.y + xo1;
            float gv = tanhf(pg);
            float iv = 1.f / (1.f + expf(-pi));
            float fv = 1.f / (1.f + expf(-pf));
            float ov = 1.f / (1.f + expf(-po));
            c1v = fmaf(gv, iv, c1v * fv);
            hv1 = tanhf(c1v) * ov;
        }

        // pair values with lane neighbor, push 8B to every cluster CTA's hnext
        float n0v = __shfl_xor_sync(0xffffffffu, hv0, 1);
        float n1v = __shfl_xor_sync(0xffffffffu, hv1, 1);
        unsigned long long pv = evenlane ? pack2(hv0, n0v) : pack2(n1v, hv1);
        uint32_t laddr = s2u(&hnext[st_row * HH + st_col]);
#pragma unroll
        for (int pr = 0; pr < CLUSTER; pr++) st_cluster_u64(laddr, pr, pv);

        if (t == SS - 1) {
            g_Hfin[(size_t)(b0 + rown0) * HH + (j0 + jj)] = hv0;
            g_Hfin[(size_t)(b0 + rown0 + 1) * HH + (j0 + jj)] = hv1;
        }

        asm volatile("barrier.cluster.arrive.aligned;" ::: "memory");
        asm volatile("barrier.cluster.wait.aligned;" ::: "memory");
    }
}

// ---------- final projection + softmax ----------
__global__ __launch_bounds__(128) void proj_softmax(const float* __restrict__ Wph,
                                                    const float* __restrict__ Wphb,
                                                    const float* __restrict__ bp,
                                                    float* __restrict__ out) {
    __shared__ float hsh[HH];
    __shared__ float red[OO];
    const int b = blockIdx.x;
    const int o = threadIdx.x;
    hsh[o]       = g_Hfin[(size_t)b * HH + o];
    hsh[o + 128] = g_Hfin[(size_t)b * HH + o + 128];
    __syncthreads();

    float acc = 0.f;
    const float* wr = Wph + (size_t)o * HH;
#pragma unroll 8
    for (int k = 0; k < HH; k += 4) {
        float4 w = *(const float4*)&wr[k];
        acc = fmaf(hsh[k],   w.x, acc);
        acc = fmaf(hsh[k+1], w.y, acc);
        acc = fmaf(hsh[k+2], w.z, acc);
        acc = fmaf(hsh[k+3], w.w, acc);
    }
    float pv = acc + Wphb[o] + bp[(size_t)b * OO + o];

    red[o] = pv;
    __syncthreads();
#pragma unroll
    for (int s = 64; s > 0; s >>= 1) {
        if (o < s) red[o] = fmaxf(red[o], red[o + s]);
        __syncthreads();
    }
    float mx = red[0];
    __syncthreads();
    float e = expf(pv - mx);
    red[o] = e;
    __syncthreads();
#pragma unroll
    for (int s = 64; s > 0; s >>= 1) {
        if (o < s) red[o] += red[o + s];
        __syncthreads();
    }
    out[(size_t)b * OO + o] = e / red[0];
}

// ---------- launch ----------
extern "C" void kernel_launch(void* const* d_in, const int* in_sizes, int n_in,
                              void* d_out, int out_size) {
    (void)in_sizes; (void)n_in; (void)out_size;
    const float* x     = (const float*)d_in[0];
    const float* Wgx_w = (const float*)d_in[1];  const float* Wgx_b = (const float*)d_in[2];
    const float* Wgh_w = (const float*)d_in[3];  const float* Wgh_b = (const float*)d_in[4];
    const float* Wix_w = (const float*)d_in[5];  const float* Wix_b = (const float*)d_in[6];
    const float* Wih_w = (const float*)d_in[7];  const float* Wih_b = (const float*)d_in[8];
    const float* Wfx_w = (const float*)d_in[9];  const float* Wfx_b = (const float*)d_in[10];
    const float* Wfh_w = (const float*)d_in[11]; const float* Wfh_b = (const float*)d_in[12];
    const float* Wox_w = (const float*)d_in[13]; const float* Wox_b = (const float*)d_in[14];
    const float* Woh_w = (const float*)d_in[15]; const float* Woh_b = (const float*)d_in[16];
    const float* Wph_w = (const float*)d_in[17]; const float* Wph_b = (const float*)d_in[18];
    const float* bg    = (const float*)d_in[19];
    const float* bi    = (const float*)d_in[20];
    const float* bf    = (const float*)d_in[21];
    const float* bo    = (const float*)d_in[22];
    const float* bp    = (const float*)d_in[23];
    float* out = (float*)d_out;

    static bool attr_done = false;
    if (!attr_done) {
        cudaFuncSetAttribute(scan_kernel, cudaFuncAttributeMaxDynamicSharedMemorySize, SCAN_SMEM);
        attr_done = true;
    }

    P1Params p1;
    p1.x = x;
    p1.Wx[0] = Wgx_w; p1.Wx[1] = Wix_w; p1.Wx[2] = Wfx_w; p1.Wx[3] = Wox_w;
    p1.Wxb[0] = Wgx_b; p1.Wxb[1] = Wix_b; p1.Wxb[2] = Wfx_b; p1.Wxb[3] = Wox_b;
    p1.Whb[0] = Wgh_b; p1.Whb[1] = Wih_b; p1.Whb[2] = Wfh_b; p1.Whb[3] = Woh_b;
    p1.bgate[0] = bg; p1.bgate[1] = bi; p1.bgate[2] = bf; p1.bgate[3] = bo;

    ScanParams sp;
    sp.Wh[0] = Wgh_w; sp.Wh[1] = Wih_w; sp.Wh[2] = Wfh_w; sp.Wh[3] = Woh_w;

    dim3 g1(NCOL / 128, (BB * SS) / 128);
    p1_gemm<<<g1, 256>>>(p1);
    scan_kernel<<<128, 256, SCAN_SMEM>>>(sp);
    proj_softmax<<<BB, OO>>>(Wph_w, Wph_b, bp, out);
}

// round 10
// speedup vs baseline: 1.4088x; 1.4088x over previous
#include <cuda_runtime.h>
#include <math.h>
#include <stdint.h>

#define BB 256
#define SS 512
#define DD 256
#define HH 256
#define OO 128
#define NCOL 1024            // 4 gates * HH
#define ROWS_PER_CTA 16
#define JS 32                // hidden-j slice per scan CTA
#define CLS 128              // 4 gates * JS (interleaved [k][jj*4+g])
#define NGROUPS 16
#define TSCAN 512
// Ws (128KB) + hs (16KB) + exchange (16 rows * 4 kq * 64 ull = 32KB)
#define EX_ULL (16 * 4 * 64)
#define SCAN_SMEM ((HH*CLS + ROWS_PER_CTA*HH) * 4 + EX_ULL * 8)

// ---------- device scratch (static; no runtime allocation) ----------
__device__ float g_XP[(size_t)SS * BB * NCOL];   // [s][b][n], n = gate*256 + j
__device__ float g_H[2][BB * HH];
__device__ unsigned g_barCnt[NGROUPS];

struct P1Params {
    const float* x;
    const float* Wx[4];
    const float* Wxb[4];
    const float* Whb[4];
    const float* bgate[4];
};
struct ScanParams { const float* Wh[4]; };

// ---------- packed f32x2 helpers (Blackwell FFMA2) ----------
__device__ __forceinline__ unsigned long long pack2(float lo, float hi) {
    unsigned long long r;
    asm("mov.b64 %0, {%1, %2};"
        : "=l"(r) : "r"(__float_as_uint(lo)), "r"(__float_as_uint(hi)));
    return r;
}
__device__ __forceinline__ void fma2(unsigned long long& d,
                                     unsigned long long a, unsigned long long b) {
    asm("fma.rn.f32x2 %0, %1, %2, %0;" : "+l"(d) : "l"(a), "l"(b));
}
__device__ __forceinline__ void add2(unsigned long long& d, unsigned long long a) {
    asm("add.rn.f32x2 %0, %0, %1;" : "+l"(d) : "l"(a));
}
__device__ __forceinline__ float2 unpack2(unsigned long long v) {
    unsigned lo, hi;
    asm("mov.b64 {%0, %1}, %2;" : "=r"(lo), "=r"(hi) : "l"(v));
    return make_float2(__uint_as_float(lo), __uint_as_float(hi));
}

// ---------- init: zero h0 + barrier counters ----------
__global__ __launch_bounds__(256) void init_kernel() {
    unsigned i = blockIdx.x * blockDim.x + threadIdx.x;
    if (i < (unsigned)(BB * HH)) g_H[0][i] = 0.f;
    if (i < NGROUPS) g_barCnt[i] = 0u;
}

// ---------- phase 1: XP = x @ Wx^T + (Wx_b + Wh_b) + bgate ----------
// M=131072, N=1024, K=256. 128x128 tile, 256 thr, 8x8 per thread (FFMA2).
__global__ __launch_bounds__(256, 2) void p1_gemm(P1Params p) {
    __shared__ __align__(16) float As[16][132];
    __shared__ __align__(16) float Bs[16][132];
    const int tid = threadIdx.x;
    const int tm = tid >> 4, tn = tid & 15;
    const int ml = tid >> 2;
    const int kl = (tid & 3) * 4;
    const int g   = blockIdx.x >> 1;
    const int j0g = (blockIdx.x & 1) * 128;

    const float* Aptr0 = p.x + (size_t)(blockIdx.y * 128 + ml) * DD + kl;
    const float* Aptr1 = Aptr0 + (size_t)64 * DD;
    const float* Bptr0 = p.Wx[g] + (size_t)(j0g + ml) * DD + kl;
    const float* Bptr1 = Bptr0 + (size_t)64 * DD;

    unsigned long long acc[8][4];
#pragma unroll
    for (int r = 0; r < 8; r++)
#pragma unroll
        for (int c = 0; c < 4; c++) acc[r][c] = 0ull;

    for (int kt = 0; kt < DD; kt += 16) {
        float4 a0 = *(const float4*)(Aptr0 + kt);
        float4 a1 = *(const float4*)(Aptr1 + kt);
        float4 b0 = *(const float4*)(Bptr0 + kt);
        float4 b1 = *(const float4*)(Bptr1 + kt);
        As[kl+0][ml] = a0.x; As[kl+1][ml] = a0.y; As[kl+2][ml] = a0.z; As[kl+3][ml] = a0.w;
        As[kl+0][ml+64] = a1.x; As[kl+1][ml+64] = a1.y; As[kl+2][ml+64] = a1.z; As[kl+3][ml+64] = a1.w;
        Bs[kl+0][ml] = b0.x; Bs[kl+1][ml] = b0.y; Bs[kl+2][ml] = b0.z; Bs[kl+3][ml] = b0.w;
        Bs[kl+0][ml+64] = b1.x; Bs[kl+1][ml+64] = b1.y; Bs[kl+2][ml+64] = b1.z; Bs[kl+3][ml+64] = b1.w;
        __syncthreads();
#pragma unroll
        for (int kk = 0; kk < 16; kk++) {
            float4 av0 = *(const float4*)&As[kk][tm * 8];
            float4 av1 = *(const float4*)&As[kk][tm * 8 + 4];
            ulonglong2 bv0 = *(const ulonglong2*)&Bs[kk][tn * 8];
            ulonglong2 bv1 = *(const ulonglong2*)&Bs[kk][tn * 8 + 4];
            float ar[8] = {av0.x, av0.y, av0.z, av0.w, av1.x, av1.y, av1.z, av1.w};
#pragma unroll
            for (int r = 0; r < 8; r++) {
                unsigned long long ap = pack2(ar[r], ar[r]);
                fma2(acc[r][0], ap, bv0.x);
                fma2(acc[r][1], ap, bv0.y);
                fma2(acc[r][2], ap, bv1.x);
                fma2(acc[r][3], ap, bv1.y);
            }
        }
        __syncthreads();
    }

    const int jc = j0g + tn * 8;
    const int n0 = blockIdx.x * 128 + tn * 8;
    float4 wbl = *(const float4*)&p.Wxb[g][jc];
    float4 wbh = *(const float4*)&p.Wxb[g][jc + 4];
    float4 hbl = *(const float4*)&p.Whb[g][jc];
    float4 hbh = *(const float4*)&p.Whb[g][jc + 4];
    wbl.x += hbl.x; wbl.y += hbl.y; wbl.z += hbl.z; wbl.w += hbl.w;
    wbh.x += hbh.x; wbh.y += hbh.y; wbh.z += hbh.z; wbh.w += hbh.w;
#pragma unroll
    for (int rr = 0; rr < 8; rr++) {
        int m = blockIdx.y * 128 + tm * 8 + rr;
        int b = m >> 9;
        int s = m & 511;
        float4 bgl = *(const float4*)(p.bgate[g] + (size_t)b * HH + jc);
        float4 bgh = *(const float4*)(p.bgate[g] + (size_t)b * HH + jc + 4);
        float2 p0 = unpack2(acc[rr][0]);
        float2 p1 = unpack2(acc[rr][1]);
        float2 p2 = unpack2(acc[rr][2]);
        float2 p3 = unpack2(acc[rr][3]);
        float4 o0 = make_float4(p0.x + wbl.x + bgl.x, p0.y + wbl.y + bgl.y,
                                p1.x + wbl.z + bgl.z, p1.y + wbl.w + bgl.w);
        float4 o1 = make_float4(p2.x + wbh.x + bgh.x, p2.y + wbh.y + bgh.y,
                                p3.x + wbh.z + bgh.z, p3.y + wbh.w + bgh.w);
        float* dst = &g_XP[((size_t)s * BB + b) * NCOL + n0];
        *(float4*)dst = o0;
        *(float4*)(dst + 4) = o1;
    }
}

// ---------- persistent recurrent scan (512 threads, 4-way k-split) ----------
// 128 CTAs: rb owns batch rows [rb*16,+16); cb owns j in [cb*32,+32).
// Warp (kq, rg): 4 rows of rowgroup rg over k-quarter kq. Each thread owns
// final output row rbase+kq, col j0+jj. Partial sums merged via 32KB smem.
// h exchanged through double-buffered global g_H; monotonic-counter barrier.
__global__ __launch_bounds__(TSCAN, 1) void scan_kernel(ScanParams p) {
    extern __shared__ __align__(16) float smem_f[];
    float* Ws = smem_f;                              // [k][c] 256*128
    float* hs = Ws + HH * CLS;                       // [16][256]
    unsigned long long* ex = (unsigned long long*)(hs + ROWS_PER_CTA * HH);

    const int tid = threadIdx.x;
    const int cb = blockIdx.x & 7;
    const int rb = blockIdx.x >> 3;
    const int b0 = rb * ROWS_PER_CTA;
    const int j0 = cb * JS;

    // Ws load, gate-interleaved: Ws[k*128 + jj*4 + g] = Wh_g[j0+jj][k]
    for (int idx = tid; idx < CLS * HH; idx += TSCAN) {
        int k = idx >> 7;
        int c = idx & 127;
        int jjx = c >> 2;
        int gx = c & 3;
        Ws[k * CLS + c] = p.Wh[gx][(size_t)(j0 + jjx) * HH + k];
    }
    __syncthreads();

    const int jj = tid & 31;
    const int warp = tid >> 5;
    const int rg = warp & 3;            // row group (4 rows)
    const int kq = warp >> 2;           // k quarter (64 ks)
    const int rbase = rg * 4;
    const int k0 = kq * 64;
    const int rown = rbase + kq;        // owned output row
    float cv = 0.f;                     // cell state (register)

    const float* wrow = Ws + (size_t)k0 * CLS + jj * 4;
    const int exrow = rg * 4;           // row-slot base for this rowgroup

    for (int t = 0; t < SS; t++) {
        // Hin load into hs (L2-direct)
        {
            const float* Hin = g_H[t & 1];
            int base = tid * 8;
            int row = base >> 8, col = base & 255;
            const float4* src = (const float4*)&Hin[(size_t)(b0 + row) * HH + col];
            float4 va = __ldcg(src);
            float4 vb = __ldcg(src + 1);
            *(float4*)&hs[base] = va;
            *(float4*)&hs[base + 4] = vb;
        }
        // prefetch this step's xp for the owned row (4 gates)
        const float* xpr = g_XP + ((size_t)t * BB + b0 + rown) * NCOL + j0 + jj;
        float xg = xpr[0], xi = xpr[256], xf = xpr[512], xo = xpr[768];
        __syncthreads();

        unsigned long long aGI[4] = {0ull, 0ull, 0ull, 0ull};
        unsigned long long aFO[4] = {0ull, 0ull, 0ull, 0ull};
        const float* h0 = hs + (rbase + 0) * HH + k0;
        const float* h1 = h0 + HH;
        const float* h2 = h1 + HH;
        const float* h3 = h2 + HH;
#define KSTEP(C, KK)                                                          \
        {                                                                     \
            ulonglong2 wp = *(const ulonglong2*)&wrow[(size_t)(KK) * CLS];    \
            unsigned long long q0 = pack2(v0.C, v0.C);                        \
            unsigned long long q1 = pack2(v1.C, v1.C);                        \
            unsigned long long q2 = pack2(v2.C, v2.C);                        \
            unsigned long long q3 = pack2(v3.C, v3.C);                        \
            fma2(aGI[0], q0, wp.x); fma2(aFO[0], q0, wp.y);                   \
            fma2(aGI[1], q1, wp.x); fma2(aFO[1], q1, wp.y);                   \
            fma2(aGI[2], q2, wp.x); fma2(aFO[2], q2, wp.y);                   \
            fma2(aGI[3], q3, wp.x); fma2(aFO[3], q3, wp.y);                   \
        }
#pragma unroll 4
        for (int k4 = 0; k4 < 64; k4 += 4) {
            float4 v0 = *(const float4*)&h0[k4];
            float4 v1 = *(const float4*)&h1[k4];
            float4 v2 = *(const float4*)&h2[k4];
            float4 v3 = *(const float4*)&h3[k4];
            KSTEP(x, k4 + 0)
            KSTEP(y, k4 + 1)
            KSTEP(z, k4 + 2)
            KSTEP(w, k4 + 3)
        }
#undef KSTEP

        // publish all 4 row-partials; owner sums its row's 4 k-quarters
#pragma unroll
        for (int r = 0; r < 4; r++) {
            unsigned long long* slot = ex + (size_t)((exrow + r) * 4 + kq) * 64 + jj;
            slot[0]  = aGI[r];
            slot[32] = aFO[r];
        }
        __syncthreads();

        unsigned long long GI, FO;
        {
            const unsigned long long* rsl = ex + (size_t)((exrow + kq) * 4) * 64 + jj;
            GI = rsl[0];   FO = rsl[32];
            add2(GI, rsl[64]);  add2(FO, rsl[96]);
            add2(GI, rsl[128]); add2(FO, rsl[160]);
            add2(GI, rsl[192]); add2(FO, rsl[224]);
        }

        // gate math in-register for the 1 owned row
        float2 gi = unpack2(GI);
        float2 fo = unpack2(FO);
        float pg = gi.x + xg, pi = gi.y + xi, pf = fo.x + xf, po = fo.y + xo;
        float gv = tanhf(pg);
        float iv = 1.f / (1.f + expf(-pi));
        float fv = 1.f / (1.f + expf(-pf));
        float ov = 1.f / (1.f + expf(-po));
        cv = fmaf(gv, iv, cv * fv);
        float hv = tanhf(cv) * ov;
        __stcg(&g_H[(t + 1) & 1][(size_t)(b0 + rown) * HH + (j0 + jj)], hv);

        __syncthreads();
        if (tid == 0) {
            __threadfence();                                 // release (+IVALL)
            unsigned old = atomicAdd(&g_barCnt[rb], 1u);
            unsigned target = 8u * (unsigned)(t + 1);
            if (old + 1u < target) {
                while (*(volatile unsigned*)&g_barCnt[rb] < target) { }
            }
            __threadfence();                                 // acquire (+IVALL)
        }
        __syncthreads();
    }
}

// ---------- final projection + softmax ----------
__global__ __launch_bounds__(128) void proj_softmax(const float* __restrict__ Wph,
                                                    const float* __restrict__ Wphb,
                                                    const float* __restrict__ bp,
                                                    float* __restrict__ out) {
    __shared__ float hsh[HH];
    __shared__ float red[OO];
    const int b = blockIdx.x;
    const int o = threadIdx.x;
    const float* Hfin = g_H[0];           // after t=511, buffer (512 & 1) == 0
    hsh[o]       = Hfin[(size_t)b * HH + o];
    hsh[o + 128] = Hfin[(size_t)b * HH + o + 128];
    __syncthreads();

    float acc = 0.f;
    const float* wr = Wph + (size_t)o * HH;
#pragma unroll 8
    for (int k = 0; k < HH; k += 4) {
        float4 w = *(const float4*)&wr[k];
        acc = fmaf(hsh[k],   w.x, acc);
        acc = fmaf(hsh[k+1], w.y, acc);
        acc = fmaf(hsh[k+2], w.z, acc);
        acc = fmaf(hsh[k+3], w.w, acc);
    }
    float pv = acc + Wphb[o] + bp[(size_t)b * OO + o];

    red[o] = pv;
    __syncthreads();
#pragma unroll
    for (int s = 64; s > 0; s >>= 1) {
        if (o < s) red[o] = fmaxf(red[o], red[o + s]);
        __syncthreads();
    }
    float mx = red[0];
    __syncthreads();
    float e = expf(pv - mx);
    red[o] = e;
    __syncthreads();
#pragma unroll
    for (int s = 64; s > 0; s >>= 1) {
        if (o < s) red[o] += red[o + s];
        __syncthreads();
    }
    out[(size_t)b * OO + o] = e / red[0];
}

// ---------- launch ----------
extern "C" void kernel_launch(void* const* d_in, const int* in_sizes, int n_in,
                              void* d_out, int out_size) {
    (void)in_sizes; (void)n_in; (void)out_size;
    const float* x     = (const float*)d_in[0];
    const float* Wgx_w = (const float*)d_in[1];  const float* Wgx_b = (const float*)d_in[2];
    const float* Wgh_w = (const float*)d_in[3];  const float* Wgh_b = (const float*)d_in[4];
    const float* Wix_w = (const float*)d_in[5];  const float* Wix_b = (const float*)d_in[6];
    const float* Wih_w = (const float*)d_in[7];  const float* Wih_b = (const float*)d_in[8];
    const float* Wfx_w = (const float*)d_in[9];  const float* Wfx_b = (const float*)d_in[10];
    const float* Wfh_w = (const float*)d_in[11]; const float* Wfh_b = (const float*)d_in[12];
    const float* Wox_w = (const float*)d_in[13]; const float* Wox_b = (const float*)d_in[14];
    const float* Woh_w = (const float*)d_in[15]; const float* Woh_b = (const float*)d_in[16];
    const float* Wph_w = (const float*)d_in[17]; const float* Wph_b = (const float*)d_in[18];
    const float* bg    = (const float*)d_in[19];
    const float* bi    = (const float*)d_in[20];
    const float* bf    = (const float*)d_in[21];
    const float* bo    = (const float*)d_in[22];
    const float* bp    = (const float*)d_in[23];
    float* out = (float*)d_out;

    static bool attr_done = false;
    if (!attr_done) {
        cudaFuncSetAttribute(scan_kernel, cudaFuncAttributeMaxDynamicSharedMemorySize, SCAN_SMEM);
        attr_done = true;
    }

    P1Params p1;
    p1.x = x;
    p1.Wx[0] = Wgx_w; p1.Wx[1] = Wix_w; p1.Wx[2] = Wfx_w; p1.Wx[3] = Wox_w;
    p1.Wxb[0] = Wgx_b; p1.Wxb[1] = Wix_b; p1.Wxb[2] = Wfx_b; p1.Wxb[3] = Wox_b;
    p1.Whb[0] = Wgh_b; p1.Whb[1] = Wih_b; p1.Whb[2] = Wfh_b; p1.Whb[3] = Woh_b;
    p1.bgate[0] = bg; p1.bgate[1] = bi; p1.bgate[2] = bf; p1.bgate[3] = bo;

    ScanParams sp;
    sp.Wh[0] = Wgh_w; sp.Wh[1] = Wih_w; sp.Wh[2] = Wfh_w; sp.Wh[3] = Woh_w;

    init_kernel<<<(BB * HH + 255) / 256, 256>>>();
    dim3 g1(NCOL / 128, (BB * SS) / 128);
    p1_gemm<<<g1, 256>>>(p1);
    scan_kernel<<<128, TSCAN, SCAN_SMEM>>>(sp);
    proj_softmax<<<BB, OO>>>(Wph_w, Wph_b, bp, out);
}

// round 12
// speedup vs baseline: 1.5269x; 1.0838x over previous
#include <cuda_runtime.h>
#include <cuda_bf16.h>
#include <math.h>
#include <stdint.h>

#define BB 256
#define SS 512
#define DD 256
#define HH 256
#define OO 128
#define NCOL 1024            // 4 gates * HH
#define ROWS_PER_CTA 16
#define JS 32                // hidden-j slice per scan CTA
#define NGROUPS 16
#define TSCAN 512

// scan smem layout (bytes, from dynamic smem base; base is 16B aligned)
#define APK_H 0              // A-frag packed h_hi: 16 ksteps * 32 lanes * 16B = 8192
#define APK_L 8192           // h_lo: 8192
#define PRE_OFF 16384        // pre staging: 128 * 17 * 4 = 8704
#define BPK_H 25088          // B-frag packed W_hi: 16 nblk * 16 kstep * 32 * 8B = 65536
#define BPK_L 90624          // W_lo: 65536  -> ends 156160
#define SCAN_SMEM 156160

// ---------- device scratch ----------
__device__ float g_XP[(size_t)SS * BB * NCOL];   // [s][b][n], n = gate*256 + j
__device__ float g_H[2][BB * HH];
__device__ unsigned g_barCnt[NGROUPS];

struct P1Params {
    const float* x;
    const float* Wx[4];
    const float* Wxb[4];
    const float* Whb[4];
    const float* bgate[4];
};
struct ScanParams { const float* Wh[4]; };

// ---------- packed f32x2 helpers (Blackwell FFMA2) ----------
__device__ __forceinline__ unsigned long long pack2(float lo, float hi) {
    unsigned long long r;
    asm("mov.b64 %0, {%1, %2};"
        : "=l"(r) : "r"(__float_as_uint(lo)), "r"(__float_as_uint(hi)));
    return r;
}
__device__ __forceinline__ void fma2(unsigned long long& d,
                                     unsigned long long a, unsigned long long b) {
    asm("fma.rn.f32x2 %0, %1, %2, %0;" : "+l"(d) : "l"(a), "l"(b));
}
__device__ __forceinline__ float2 unpack2(unsigned long long v) {
    unsigned lo, hi;
    asm("mov.b64 {%0, %1}, %2;" : "=r"(lo), "=r"(hi) : "l"(v));
    return make_float2(__uint_as_float(lo), __uint_as_float(hi));
}

// ---------- bf16 mma.sync (baseline PTX, works at compute_103) ----------
__device__ __forceinline__ void mma16816(float c[4],
                                         uint32_t a0, uint32_t a1, uint32_t a2, uint32_t a3,
                                         uint32_t b0, uint32_t b1) {
    asm volatile(
        "mma.sync.aligned.m16n8k16.row.col.f32.bf16.bf16.f32 "
        "{%0,%1,%2,%3}, {%4,%5,%6,%7}, {%8,%9}, {%0,%1,%2,%3};"
        : "+f"(c[0]), "+f"(c[1]), "+f"(c[2]), "+f"(c[3])
        : "r"(a0), "r"(a1), "r"(a2), "r"(a3), "r"(b0), "r"(b1));
}
__device__ __forceinline__ uint32_t bfpair(float x, float y) {
    __nv_bfloat162 p;
    p.x = __float2bfloat16_rn(x);
    p.y = __float2bfloat16_rn(y);
    return *(uint32_t*)&p;
}

// ---------- init: zero h0 + barrier counters ----------
__global__ __launch_bounds__(256) void init_kernel() {
    unsigned i = blockIdx.x * blockDim.x + threadIdx.x;
    if (i < (unsigned)(BB * HH)) g_H[0][i] = 0.f;
    if (i < NGROUPS) g_barCnt[i] = 0u;
}

// ---------- phase 1: XP = x @ Wx^T + (Wx_b + Wh_b) + bgate (proven FFMA2) ----------
__global__ __launch_bounds__(256, 2) void p1_gemm(P1Params p) {
    __shared__ __align__(16) float As[16][132];
    __shared__ __align__(16) float Bs[16][132];
    const int tid = threadIdx.x;
    const int tm = tid >> 4, tn = tid & 15;
    const int ml = tid >> 2;
    const int kl = (tid & 3) * 4;
    const int g   = blockIdx.x >> 1;
    const int j0g = (blockIdx.x & 1) * 128;

    const float* Aptr0 = p.x + (size_t)(blockIdx.y * 128 + ml) * DD + kl;
    const float* Aptr1 = Aptr0 + (size_t)64 * DD;
    const float* Bptr0 = p.Wx[g] + (size_t)(j0g + ml) * DD + kl;
    const float* Bptr1 = Bptr0 + (size_t)64 * DD;

    unsigned long long acc[8][4];
#pragma unroll
    for (int r = 0; r < 8; r++)
#pragma unroll
        for (int c = 0; c < 4; c++) acc[r][c] = 0ull;

    for (int kt = 0; kt < DD; kt += 16) {
        float4 a0 = *(const float4*)(Aptr0 + kt);
        float4 a1 = *(const float4*)(Aptr1 + kt);
        float4 b0 = *(const float4*)(Bptr0 + kt);
        float4 b1 = *(const float4*)(Bptr1 + kt);
        As[kl+0][ml] = a0.x; As[kl+1][ml] = a0.y; As[kl+2][ml] = a0.z; As[kl+3][ml] = a0.w;
        As[kl+0][ml+64] = a1.x; As[kl+1][ml+64] = a1.y; As[kl+2][ml+64] = a1.z; As[kl+3][ml+64] = a1.w;
        Bs[kl+0][ml] = b0.x; Bs[kl+1][ml] = b0.y; Bs[kl+2][ml] = b0.z; Bs[kl+3][ml] = b0.w;
        Bs[kl+0][ml+64] = b1.x; Bs[kl+1][ml+64] = b1.y; Bs[kl+2][ml+64] = b1.z; Bs[kl+3][ml+64] = b1.w;
        __syncthreads();
#pragma unroll
        for (int kk = 0; kk < 16; kk++) {
            float4 av0 = *(const float4*)&As[kk][tm * 8];
            float4 av1 = *(const float4*)&As[kk][tm * 8 + 4];
            ulonglong2 bv0 = *(const ulonglong2*)&Bs[kk][tn * 8];
            ulonglong2 bv1 = *(const ulonglong2*)&Bs[kk][tn * 8 + 4];
            float ar[8] = {av0.x, av0.y, av0.z, av0.w, av1.x, av1.y, av1.z, av1.w};
#pragma unroll
            for (int r = 0; r < 8; r++) {
                unsigned long long ap = pack2(ar[r], ar[r]);
                fma2(acc[r][0], ap, bv0.x);
                fma2(acc[r][1], ap, bv0.y);
                fma2(acc[r][2], ap, bv1.x);
                fma2(acc[r][3], ap, bv1.y);
            }
        }
        __syncthreads();
    }

    const int jc = j0g + tn * 8;
    const int n0 = blockIdx.x * 128 + tn * 8;
    float4 wbl = *(const float4*)&p.Wxb[g][jc];
    float4 wbh = *(const float4*)&p.Wxb[g][jc + 4];
    float4 hbl = *(const float4*)&p.Whb[g][jc];
    float4 hbh = *(const float4*)&p.Whb[g][jc + 4];
    wbl.x += hbl.x; wbl.y += hbl.y; wbl.z += hbl.z; wbl.w += hbl.w;
    wbh.x += hbh.x; wbh.y += hbh.y; wbh.z += hbh.z; wbh.w += hbh.w;
#pragma unroll
    for (int rr = 0; rr < 8; rr++) {
        int m = blockIdx.y * 128 + tm * 8 + rr;
        int b = m >> 9;
        int s = m & 511;
        float4 bgl = *(const float4*)(p.bgate[g] + (size_t)b * HH + jc);
        float4 bgh = *(const float4*)(p.bgate[g] + (size_t)b * HH + jc + 4);
        float2 p0 = unpack2(acc[rr][0]);
        float2 p1 = unpack2(acc[rr][1]);
        float2 p2 = unpack2(acc[rr][2]);
        float2 p3 = unpack2(acc[rr][3]);
        float4 o0 = make_float4(p0.x + wbl.x + bgl.x, p0.y + wbl.y + bgl.y,
                                p1.x + wbl.z + bgl.z, p1.y + wbl.w + bgl.w);
        float4 o1 = make_float4(p2.x + wbh.x + bgh.x, p2.y + wbh.y + bgh.y,
                                p3.x + wbh.z + bgh.z, p3.y + wbh.w + bgh.w);
        float* dst = &g_XP[((size_t)s * BB + b) * NCOL + n0];
        *(float4*)dst = o0;
        *(float4*)(dst + 4) = o1;
    }
}

// ---------- persistent recurrent scan: bf16-split HMMA (mma.sync) ----------
// 128 CTAs: rb owns batch rows [rb*16,+16); cb owns j in [cb*32,+32).
// W' [n][k], n = g*32+jj, pre-packed once into B-fragment layout (hi+lo bf16).
// Per step: h fp32 -> A-fragment-packed bf16 hi/lo; 16 warps x (1 n-block x
// 3 split terms x 16 ksteps) mma.sync accumulating fp32; stage D -> smem;
// gate math 1 cell/thread (state in register); gmem monotone barrier.
__global__ __launch_bounds__(TSCAN, 1) void scan_kernel(ScanParams p) {
    extern __shared__ __align__(16) char smem[];
    uint32_t* apk_h = (uint32_t*)(smem + APK_H);
    uint32_t* apk_l = (uint32_t*)(smem + APK_L);
    float*    pre   = (float*)(smem + PRE_OFF);
    uint32_t* bpk_h = (uint32_t*)(smem + BPK_H);
    uint32_t* bpk_l = (uint32_t*)(smem + BPK_L);

    const int tid = threadIdx.x;
    const int cb = blockIdx.x & 7;
    const int rb = blockIdx.x >> 3;
    const int b0 = rb * ROWS_PER_CTA;
    const int j0 = cb * JS;
    const int lane = tid & 31;
    const int warp = tid >> 5;

    // One-time W pre-pack into B-fragment order.
    // slot s in [0,8192): nblk=s>>9, ks=(s>>5)&15, ln=s&31.
    // n = nblk*8 + ln/4 (n = g*32 + jj), q = ln&3, k0 = ks*16 + 2q.
    // slot holds 2 b32: {W[n][k0],W[n][k0+1]}, {W[n][k0+8],W[n][k0+9]}.
    for (int s = tid; s < 8192; s += TSCAN) {
        int nblk = s >> 9;
        int ks = (s >> 5) & 15;
        int ln = s & 31;
        int n = nblk * 8 + (ln >> 2);
        int g = n >> 5;
        int jjx = n & 31;
        int k0 = ks * 16 + (ln & 3) * 2;
        const float* wr = p.Wh[g] + (size_t)(j0 + jjx) * HH;
        float2 fa = *(const float2*)&wr[k0];
        float2 fb = *(const float2*)&wr[k0 + 8];
        uint32_t ha = bfpair(fa.x, fa.y);
        uint32_t hb = bfpair(fb.x, fb.y);
        float ra0 = fa.x - __bfloat162float(__float2bfloat16_rn(fa.x));
        float ra1 = fa.y - __bfloat162float(__float2bfloat16_rn(fa.y));
        float rb0 = fb.x - __bfloat162float(__float2bfloat16_rn(fb.x));
        float rb1 = fb.y - __bfloat162float(__float2bfloat16_rn(fb.y));
        bpk_h[s * 2]     = ha;
        bpk_h[s * 2 + 1] = hb;
        bpk_l[s * 2]     = bfpair(ra0, ra1);
        bpk_l[s * 2 + 1] = bfpair(rb0, rb1);
    }
    __syncthreads();

    // per-thread gate-cell ownership (epilogue)
    const int row = tid >> 5;       // batch row 0..15
    const int jj = tid & 31;        // hidden unit
    float cv = 0.f;                 // cell state (register)

    // warp's B-fragment base (warp == nblk)
    const uint32_t* bh_base = bpk_h + (size_t)warp * 16 * 64; // 16 ksteps * 32 lanes * 2
    const uint32_t* bl_base = bpk_l + (size_t)warp * 16 * 64;

    for (int t = 0; t < SS; t++) {
        // h(t) fp32 -> A-fragment-packed bf16 hi/lo (4 k-pair units / thread)
        {
            const float* Hin = g_H[t & 1];
#pragma unroll
            for (int q = 0; q < 4; q++) {
                int u = tid * 4 + q;            // unit: (r, kp)
                int r = u >> 7;
                int kp = u & 127;
                float2 hv = __ldcg((const float2*)&Hin[(size_t)(b0 + r) * HH + kp * 2]);
                int ks = kp >> 3;
                int kq = kp & 7;
                int dl = (r & 7) * 4 + (kq & 3);            // dest lane
                int reg = (r >> 3) + ((kq >> 2) << 1);      // a0..a3 position
                int addr = ks * 128 + dl * 4 + reg;         // in b32 units
                apk_h[addr] = bfpair(hv.x, hv.y);
                float r0 = hv.x - __bfloat162float(__float2bfloat16_rn(hv.x));
                float r1 = hv.y - __bfloat162float(__float2bfloat16_rn(hv.y));
                apk_l[addr] = bfpair(r0, r1);
            }
        }
        // xp prefetch for owned cell (4 gates)
        const float* xpr = g_XP + ((size_t)t * BB + b0 + row) * NCOL + j0 + jj;
        float xg = __ldcg(xpr);
        float xi = __ldcg(xpr + 256);
        float xf = __ldcg(xpr + 512);
        float xo = __ldcg(xpr + 768);
        __syncthreads();

        // mainloop: 16 ksteps x (Ah*Bh + Ah*Bl + Al*Bh)
        float c[4] = {0.f, 0.f, 0.f, 0.f};
#pragma unroll
        for (int ks = 0; ks < 16; ks++) {
            uint4 ah = *(const uint4*)&apk_h[ks * 128 + lane * 4];
            uint2 bh = *(const uint2*)&bh_base[(ks * 32 + lane) * 2];
            mma16816(c, ah.x, ah.y, ah.z, ah.w, bh.x, bh.y);
            uint2 bl = *(const uint2*)&bl_base[(ks * 32 + lane) * 2];
            mma16816(c, ah.x, ah.y, ah.z, ah.w, bl.x, bl.y);
            uint4 al = *(const uint4*)&apk_l[ks * 128 + lane * 4];
            mma16816(c, al.x, al.y, al.z, al.w, bh.x, bh.y);
        }

        // stage D to smem: lane holds rows lane/4, lane/4+8; cols warp*8+(lane%4)*2+{0,1}
        {
            int r0 = lane >> 2;
            int n0 = warp * 8 + (lane & 3) * 2;
            pre[n0 * 17 + r0]           = c[0];
            pre[(n0 + 1) * 17 + r0]     = c[1];
            pre[n0 * 17 + r0 + 8]       = c[2];
            pre[(n0 + 1) * 17 + r0 + 8] = c[3];
        }
        __syncthreads();

        // gate math: one cell per thread (n = g*32 + jj)
        {
            float pg = pre[jj * 17 + row]         + xg;
            float pi = pre[(32 + jj) * 17 + row]  + xi;
            float pf = pre[(64 + jj) * 17 + row]  + xf;
            float po = pre[(96 + jj) * 17 + row]  + xo;
            float gv = tanhf(pg);
            float iv = 1.f / (1.f + expf(-pi));
            float fv = 1.f / (1.f + expf(-pf));
            float ov = 1.f / (1.f + expf(-po));
            cv = fmaf(gv, iv, cv * fv);
            float hv = tanhf(cv) * ov;
            __stcg(&g_H[(t + 1) & 1][(size_t)(b0 + row) * HH + (j0 + jj)], hv);
        }
        __syncthreads();

        // cross-CTA row-group barrier (monotone counter; proven)
        if (tid == 0) {
            __threadfence();
            unsigned old = atomicAdd(&g_barCnt[rb], 1u);
            unsigned target = 8u * (unsigned)(t + 1);
            if (old + 1u < target) {
                while (*(volatile unsigned*)&g_barCnt[rb] < target) { }
            }
            __threadfence();
        }
        __syncthreads();
    }
}

// ---------- final projection + softmax ----------
__global__ __launch_bounds__(128) void proj_softmax(const float* __restrict__ Wph,
                                                    const float* __restrict__ Wphb,
                                                    const float* __restrict__ bp,
                                                    float* __restrict__ out) {
    __shared__ float hsh[HH];
    __shared__ float red[OO];
    const int b = blockIdx.x;
    const int o = threadIdx.x;
    const float* Hfin = g_H[0];           // after t=511, buffer (512 & 1) == 0
    hsh[o]       = Hfin[(size_t)b * HH + o];
    hsh[o + 128] = Hfin[(size_t)b * HH + o + 128];
    __syncthreads();

    float acc = 0.f;
    const float* wr = Wph + (size_t)o * HH;
#pragma unroll 8
    for (int k = 0; k < HH; k += 4) {
        float4 w = *(const float4*)&wr[k];
        acc = fmaf(hsh[k],   w.x, acc);
        acc = fmaf(hsh[k+1], w.y, acc);
        acc = fmaf(hsh[k+2], w.z, acc);
        acc = fmaf(hsh[k+3], w.w, acc);
    }
    float pv = acc + Wphb[o] + bp[(size_t)b * OO + o];

    red[o] = pv;
    __syncthreads();
#pragma unroll
    for (int s = 64; s > 0; s >>= 1) {
        if (o < s) red[o] = fmaxf(red[o], red[o + s]);
        __syncthreads();
    }
    float mx = red[0];
    __syncthreads();
    float e = expf(pv - mx);
    red[o] = e;
    __syncthreads();
#pragma unroll
    for (int s = 64; s > 0; s >>= 1) {
        if (o < s) red[o] += red[o + s];
        __syncthreads();
    }
    out[(size_t)b * OO + o] = e / red[0];
}

// ---------- launch ----------
extern "C" void kernel_launch(void* const* d_in, const int* in_sizes, int n_in,
                              void* d_out, int out_size) {
    (void)in_sizes; (void)n_in; (void)out_size;
    const float* x     = (const float*)d_in[0];
    const float* Wgx_w = (const float*)d_in[1];  const float* Wgx_b = (const float*)d_in[2];
    const float* Wgh_w = (const float*)d_in[3];  const float* Wgh_b = (const float*)d_in[4];
    const float* Wix_w = (const float*)d_in[5];  const float* Wix_b = (const float*)d_in[6];
    const float* Wih_w = (const float*)d_in[7];  const float* Wih_b = (const float*)d_in[8];
    const float* Wfx_w = (const float*)d_in[9];  const float* Wfx_b = (const float*)d_in[10];
    const float* Wfh_w = (const float*)d_in[11]; const float* Wfh_b = (const float*)d_in[12];
    const float* Wox_w = (const float*)d_in[13]; const float* Wox_b = (const float*)d_in[14];
    const float* Woh_w = (const float*)d_in[15]; const float* Woh_b = (const float*)d_in[16];
    const float* Wph_w = (const float*)d_in[17]; const float* Wph_b = (const float*)d_in[18];
    const float* bg    = (const float*)d_in[19];
    const float* bi    = (const float*)d_in[20];
    const float* bf    = (const float*)d_in[21];
    const float* bo    = (const float*)d_in[22];
    const float* bp    = (const float*)d_in[23];
    float* out = (float*)d_out;

    static bool attr_done = false;
    if (!attr_done) {
        cudaFuncSetAttribute(scan_kernel, cudaFuncAttributeMaxDynamicSharedMemorySize, SCAN_SMEM);
        attr_done = true;
    }

    P1Params p1;
    p1.x = x;
    p1.Wx[0] = Wgx_w; p1.Wx[1] = Wix_w; p1.Wx[2] = Wfx_w; p1.Wx[3] = Wox_w;
    p1.Wxb[0] = Wgx_b; p1.Wxb[1] = Wix_b; p1.Wxb[2] = Wfx_b; p1.Wxb[3] = Wox_b;
    p1.Whb[0] = Wgh_b; p1.Whb[1] = Wih_b; p1.Whb[2] = Wfh_b; p1.Whb[3] = Woh_b;
    p1.bgate[0] = bg; p1.bgate[1] = bi; p1.bgate[2] = bf; p1.bgate[3] = bo;

    ScanParams sp;
    sp.Wh[0] = Wgh_w; sp.Wh[1] = Wih_w; sp.Wh[2] = Wfh_w; sp.Wh[3] = Woh_w;

    init_kernel<<<(BB * HH + 255) / 256, 256>>>();
    dim3 g1(NCOL / 128, (BB * SS) / 128);
    p1_gemm<<<g1, 256>>>(p1);
    scan_kernel<<<128, TSCAN, SCAN_SMEM>>>(sp);
    proj_softmax<<<BB, OO>>>(Wph_w, Wph_b, bp, out);
}

// round 15
// speedup vs baseline: 1.8429x; 1.2070x over previous
#include <cuda_runtime.h>
#include <cuda_bf16.h>
#include <math.h>
#include <stdint.h>

#define BB 256
#define SS 512
#define DD 256
#define HH 256
#define OO 128
#define NCOL 1024            // 4 gates * HH
#define ROWS_PER_CTA 16
#define JS 32
#define NGROUPS 16
#define TSCAN 512
#define MROWS (BB * SS)      // 131072
#define NMBLK (MROWS / 16)   // 8192
#define NNBLK (NCOL / 8)     // 128

// scan smem layout (bytes)
#define APK_H 0
#define APK_L 8192
#define PRE_OFF 16384
#define BPK_H 25088
#define BPK_L 90624
#define SCAN_SMEM 156160

// ---------- device scratch ----------
__device__ float g_XP[(size_t)SS * BB * NCOL];   // [s][b][n]
__device__ float g_H[2][BB * HH];
__device__ unsigned g_barCnt[NGROUPS];
__device__ uint4 g_XA_h[(size_t)NMBLK * 16 * 32];   // A-frag packed x hi
__device__ uint4 g_XA_l[(size_t)NMBLK * 16 * 32];   // A-frag packed x lo
__device__ uint2 g_WB_h[(size_t)NNBLK * 16 * 32];   // B-frag packed Wx hi
__device__ uint2 g_WB_l[(size_t)NNBLK * 16 * 32];   // B-frag packed Wx lo
__device__ float g_bias[NCOL];                      // Wx_b + Wh_b per col

struct ScanParams { const float* Wh[4]; };
struct CvtWParams { const float* Wx[4]; const float* Wxb[4]; const float* Whb[4]; };
struct P1MParams  { const float* bgate[4]; };

// ---------- bf16 mma.sync helpers (verified in R11 scan) ----------
__device__ __forceinline__ void mma16816(float c[4],
                                         uint32_t a0, uint32_t a1, uint32_t a2, uint32_t a3,
                                         uint32_t b0, uint32_t b1) {
    asm volatile(
        "mma.sync.aligned.m16n8k16.row.col.f32.bf16.bf16.f32 "
        "{%0,%1,%2,%3}, {%4,%5,%6,%7}, {%8,%9}, {%0,%1,%2,%3};"
        : "+f"(c[0]), "+f"(c[1]), "+f"(c[2]), "+f"(c[3])
        : "r"(a0), "r"(a1), "r"(a2), "r"(a3), "r"(b0), "r"(b1));
}
__device__ __forceinline__ uint32_t bfpair(float x, float y) {
    __nv_bfloat162 p;
    p.x = __float2bfloat16_rn(x);
    p.y = __float2bfloat16_rn(y);
    return *(uint32_t*)&p;
}
__device__ __forceinline__ float bfres(float x) {
    return x - __bfloat162float(__float2bfloat16_rn(x));
}

// ---------- init ----------
__global__ __launch_bounds__(256) void init_kernel() {
    unsigned i = blockIdx.x * blockDim.x + threadIdx.x;
    if (i < (unsigned)(BB * HH)) g_H[0][i] = 0.f;
    if (i < NGROUPS) g_barCnt[i] = 0u;
}

// ---------- convert x -> A-fragment-packed bf16 hi/lo ----------
// thread = (mblk, ks, lane). a0={r,klo} a1={r+8,klo} a2={r,khi} a3={r+8,khi}
__global__ __launch_bounds__(256) void convert_x(const float* __restrict__ x) {
    unsigned gid = blockIdx.x * 256u + threadIdx.x;
    int lane = gid & 31;
    int ks = (gid >> 5) & 15;
    int mblk = gid >> 9;
    int r = lane >> 2;
    int k0 = ks * 16 + (lane & 3) * 2;
    const float* xr  = x + (size_t)(mblk * 16 + r) * DD;
    const float* xr8 = xr + (size_t)8 * DD;
    float2 f0 = *(const float2*)&xr[k0];
    float2 f1 = *(const float2*)&xr8[k0];
    float2 f2 = *(const float2*)&xr[k0 + 8];
    float2 f3 = *(const float2*)&xr8[k0 + 8];
    uint4 hi, lo;
    hi.x = bfpair(f0.x, f0.y); lo.x = bfpair(bfres(f0.x), bfres(f0.y));
    hi.y = bfpair(f1.x, f1.y); lo.y = bfpair(bfres(f1.x), bfres(f1.y));
    hi.z = bfpair(f2.x, f2.y); lo.z = bfpair(bfres(f2.x), bfres(f2.y));
    hi.w = bfpair(f3.x, f3.y); lo.w = bfpair(bfres(f3.x), bfres(f3.y));
    size_t idx = ((size_t)mblk * 16 + ks) * 32 + lane;
    g_XA_h[idx] = hi;
    g_XA_l[idx] = lo;
}

// ---------- convert Wx -> B-fragment-packed bf16 hi/lo + fused bias ----------
// thread = (nblk, ks, lane). n = nblk*8 + lane/4; k0 = ks*16 + (lane&3)*2.
// words: {W[n][k0],W[n][k0+1]}, {W[n][k0+8],W[n][k0+9]}   (verified mapping)
__global__ __launch_bounds__(256) void convert_w(CvtWParams p) {
    unsigned gid = blockIdx.x * 256u + threadIdx.x;
    if (gid >= (unsigned)(NNBLK * 16 * 32)) return;
    int lane = gid & 31;
    int ks = (gid >> 5) & 15;
    int nblk = gid >> 9;
    int n = nblk * 8 + (lane >> 2);
    int g = n >> 8;
    int j = n & 255;
    int k0 = ks * 16 + (lane & 3) * 2;
    const float* wr = p.Wx[g] + (size_t)j * DD;
    float2 fa = *(const float2*)&wr[k0];
    float2 fb = *(const float2*)&wr[k0 + 8];
    uint2 hi, lo;
    hi.x = bfpair(fa.x, fa.y); lo.x = bfpair(bfres(fa.x), bfres(fa.y));
    hi.y = bfpair(fb.x, fb.y); lo.y = bfpair(bfres(fb.x), bfres(fb.y));
    size_t idx = ((size_t)nblk * 16 + ks) * 32 + lane;
    g_WB_h[idx] = hi;
    g_WB_l[idx] = lo;
    if (ks == 0 && (lane & 3) == 0)
        g_bias[n] = p.Wxb[g][j] + p.Whb[g][j];
}

// ---------- phase 1 GEMM on tensor cores (no smem; direct fragment LDG) ----------
// grid (8, 1024): CTA tile 128 M x 128 N, K=256. 8 warps: wm=warp>>1 (32 M),
// wn=warp&1 (64 N). 3-term bf16-split accumulate; bias + bgate in epilogue.
__global__ __launch_bounds__(256) void p1_mma(P1MParams p) {
    const int tid = threadIdx.x;
    const int lane = tid & 31;
    const int warp = tid >> 5;
    const int wm = warp >> 1;
    const int wn = warp & 1;
    const int mblk0 = blockIdx.y * 8 + wm * 2;
    const int nblk0 = blockIdx.x * 16 + wn * 8;

    float c[2][8][4];
#pragma unroll
    for (int mb = 0; mb < 2; mb++)
#pragma unroll
        for (int nb = 0; nb < 8; nb++)
#pragma unroll
            for (int q = 0; q < 4; q++) c[mb][nb][q] = 0.f;

#pragma unroll
    for (int ks = 0; ks < 16; ks++) {
        uint4 ah0 = g_XA_h[((size_t)mblk0 * 16 + ks) * 32 + lane];
        uint4 ah1 = g_XA_h[((size_t)(mblk0 + 1) * 16 + ks) * 32 + lane];
        uint4 al0 = g_XA_l[((size_t)mblk0 * 16 + ks) * 32 + lane];
        uint4 al1 = g_XA_l[((size_t)(mblk0 + 1) * 16 + ks) * 32 + lane];
#pragma unroll
        for (int nb = 0; nb < 8; nb++) {
            size_t bidx = ((size_t)(nblk0 + nb) * 16 + ks) * 32 + lane;
            uint2 bh = g_WB_h[bidx];
            uint2 bl = g_WB_l[bidx];
            mma16816(c[0][nb], ah0.x, ah0.y, ah0.z, ah0.w, bh.x, bh.y);
            mma16816(c[0][nb], ah0.x, ah0.y, ah0.z, ah0.w, bl.x, bl.y);
            mma16816(c[0][nb], al0.x, al0.y, al0.z, al0.w, bh.x, bh.y);
            mma16816(c[1][nb], ah1.x, ah1.y, ah1.z, ah1.w, bh.x, bh.y);
            mma16816(c[1][nb], ah1.x, ah1.y, ah1.z, ah1.w, bl.x, bl.y);
            mma16816(c[1][nb], al1.x, al1.y, al1.z, al1.w, bh.x, bh.y);
        }
    }

    // epilogue: c0,c1 = {row, n0..n0+1}; c2,c3 = {row+8, n0..n0+1}
    const int b = (int)(blockIdx.y >> 2);           // batch fixed per CTA
#pragma unroll
    for (int nb = 0; nb < 8; nb++) {
        int n0 = nblk0 * 8 + nb * 8 + (lane & 3) * 2;
        int g = n0 >> 8;
        int j = n0 & 255;
        float2 bias;
        bias.x = g_bias[n0]     + __ldg(&p.bgate[g][(size_t)b * HH + j]);
        bias.y = g_bias[n0 + 1] + __ldg(&p.bgate[g][(size_t)b * HH + j + 1]);
#pragma unroll
        for (int mb = 0; mb < 2; mb++) {
            int mrow = blockIdx.y * 128 + wm * 32 + mb * 16 + (lane >> 2);
            int s0 = mrow & 511;
            int s1 = (mrow + 8) & 511;
            float2 o0 = make_float2(c[mb][nb][0] + bias.x, c[mb][nb][1] + bias.y);
            float2 o1 = make_float2(c[mb][nb][2] + bias.x, c[mb][nb][3] + bias.y);
            *(float2*)&g_XP[((size_t)s0 * BB + b) * NCOL + n0] = o0;
            *(float2*)&g_XP[((size_t)s1 * BB + b) * NCOL + n0] = o1;
        }
    }
}

// ---------- persistent recurrent scan: bf16-split HMMA (proven R11) ----------
__global__ __launch_bounds__(TSCAN, 1) void scan_kernel(ScanParams p) {
    extern __shared__ __align__(16) char smem[];
    uint32_t* apk_h = (uint32_t*)(smem + APK_H);
    uint32_t* apk_l = (uint32_t*)(smem + APK_L);
    float*    pre   = (float*)(smem + PRE_OFF);
    uint32_t* bpk_h = (uint32_t*)(smem + BPK_H);
    uint32_t* bpk_l = (uint32_t*)(smem + BPK_L);

    const int tid = threadIdx.x;
    const int cb = blockIdx.x & 7;
    const int rb = blockIdx.x >> 3;
    const int b0 = rb * ROWS_PER_CTA;
    const int j0 = cb * JS;
    const int lane = tid & 31;
    const int warp = tid >> 5;

    for (int s = tid; s < 8192; s += TSCAN) {
        int nblk = s >> 9;
        int ks = (s >> 5) & 15;
        int ln = s & 31;
        int n = nblk * 8 + (ln >> 2);
        int g = n >> 5;
        int jjx = n & 31;
        int k0 = ks * 16 + (ln & 3) * 2;
        const float* wr = p.Wh[g] + (size_t)(j0 + jjx) * HH;
        float2 fa = *(const float2*)&wr[k0];
        float2 fb = *(const float2*)&wr[k0 + 8];
        bpk_h[s * 2]     = bfpair(fa.x, fa.y);
        bpk_h[s * 2 + 1] = bfpair(fb.x, fb.y);
        bpk_l[s * 2]     = bfpair(bfres(fa.x), bfres(fa.y));
        bpk_l[s * 2 + 1] = bfpair(bfres(fb.x), bfres(fb.y));
    }
    __syncthreads();

    const int row = tid >> 5;
    const int jj = tid & 31;
    float cv = 0.f;

    const uint32_t* bh_base = bpk_h + (size_t)warp * 16 * 64;
    const uint32_t* bl_base = bpk_l + (size_t)warp * 16 * 64;

    for (int t = 0; t < SS; t++) {
        {
            const float* Hin = g_H[t & 1];
#pragma unroll
            for (int q = 0; q < 4; q++) {
                int u = tid * 4 + q;
                int r = u >> 7;
                int kp = u & 127;
                float2 hv = __ldcg((const float2*)&Hin[(size_t)(b0 + r) * HH + kp * 2]);
                int ks = kp >> 3;
                int kq = kp & 7;
                int dl = (r & 7) * 4 + (kq & 3);
                int reg = (r >> 3) + ((kq >> 2) << 1);
                int addr = ks * 128 + dl * 4 + reg;
                apk_h[addr] = bfpair(hv.x, hv.y);
                apk_l[addr] = bfpair(bfres(hv.x), bfres(hv.y));
            }
        }
        const float* xpr = g_XP + ((size_t)t * BB + b0 + row) * NCOL + j0 + jj;
        float xg = __ldcg(xpr);
        float xi = __ldcg(xpr + 256);
        float xf = __ldcg(xpr + 512);
        float xo = __ldcg(xpr + 768);
        __syncthreads();

        float c[4] = {0.f, 0.f, 0.f, 0.f};
#pragma unroll
        for (int ks = 0; ks < 16; ks++) {
            uint4 ah = *(const uint4*)&apk_h[ks * 128 + lane * 4];
            uint2 bh = *(const uint2*)&bh_base[(ks * 32 + lane) * 2];
            mma16816(c, ah.x, ah.y, ah.z, ah.w, bh.x, bh.y);
            uint2 bl = *(const uint2*)&bl_base[(ks * 32 + lane) * 2];
            mma16816(c, ah.x, ah.y, ah.z, ah.w, bl.x, bl.y);
            uint4 al = *(const uint4*)&apk_l[ks * 128 + lane * 4];
            mma16816(c, al.x, al.y, al.z, al.w, bh.x, bh.y);
        }

        {
            int r0 = lane >> 2;
            int n0 = warp * 8 + (lane & 3) * 2;
            pre[n0 * 17 + r0]           = c[0];
            pre[(n0 + 1) * 17 + r0]     = c[1];
            pre[n0 * 17 + r0 + 8]       = c[2];
            pre[(n0 + 1) * 17 + r0 + 8] = c[3];
        }
        __syncthreads();

        {
            float pg = pre[jj * 17 + row]         + xg;
            float pi = pre[(32 + jj) * 17 + row]  + xi;
            float pf = pre[(64 + jj) * 17 + row]  + xf;
            float po = pre[(96 + jj) * 17 + row]  + xo;
            float gv = tanhf(pg);
            float iv = 1.f / (1.f + expf(-pi));
            float fv = 1.f / (1.f + expf(-pf));
            float ov = 1.f / (1.f + expf(-po));
            cv = fmaf(gv, iv, cv * fv);
            float hv = tanhf(cv) * ov;
            __stcg(&g_H[(t + 1) & 1][(size_t)(b0 + row) * HH + (j0 + jj)], hv);
        }
        __syncthreads();

        if (tid == 0) {
            __threadfence();
            unsigned old = atomicAdd(&g_barCnt[rb], 1u);
            unsigned target = 8u * (unsigned)(t + 1);
            if (old + 1u < target) {
                while (*(volatile unsigned*)&g_barCnt[rb] < target) { }
            }
            __threadfence();
        }
        __syncthreads();
    }
}

// ---------- final projection + softmax ----------
__global__ __launch_bounds__(128) void proj_softmax(const float* __restrict__ Wph,
                                                    const float* __restrict__ Wphb,
                                                    const float* __restrict__ bp,
                                                    float* __restrict__ out) {
    __shared__ float hsh[HH];
    __shared__ float red[OO];
    const int b = blockIdx.x;
    const int o = threadIdx.x;
    const float* Hfin = g_H[0];
    hsh[o]       = Hfin[(size_t)b * HH + o];
    hsh[o + 128] = Hfin[(size_t)b * HH + o + 128];
    __syncthreads();

    float acc = 0.f;
    const float* wr = Wph + (size_t)o * HH;
#pragma unroll 8
    for (int k = 0; k < HH; k += 4) {
        float4 w = *(const float4*)&wr[k];
        acc = fmaf(hsh[k],   w.x, acc);
        acc = fmaf(hsh[k+1], w.y, acc);
        acc = fmaf(hsh[k+2], w.z, acc);
        acc = fmaf(hsh[k+3], w.w, acc);
    }
    float pv = acc + Wphb[o] + bp[(size_t)b * OO + o];

    red[o] = pv;
    __syncthreads();
#pragma unroll
    for (int s = 64; s > 0; s >>= 1) {
        if (o < s) red[o] = fmaxf(red[o], red[o + s]);
        __syncthreads();
    }
    float mx = red[0];
    __syncthreads();
    float e = expf(pv - mx);
    red[o] = e;
    __syncthreads();
#pragma unroll
    for (int s = 64; s > 0; s >>= 1) {
        if (o < s) red[o] += red[o + s];
        __syncthreads();
    }
    out[(size_t)b * OO + o] = e / red[0];
}

// ---------- launch ----------
extern "C" void kernel_launch(void* const* d_in, const int* in_sizes, int n_in,
                              void* d_out, int out_size) {
    (void)in_sizes; (void)n_in; (void)out_size;
    const float* x     = (const float*)d_in[0];
    const float* Wgx_w = (const float*)d_in[1];  const float* Wgx_b = (const float*)d_in[2];
    const float* Wgh_w = (const float*)d_in[3];  const float* Wgh_b = (const float*)d_in[4];
    const float* Wix_w = (const float*)d_in[5];  const float* Wix_b = (const float*)d_in[6];
    const float* Wih_w = (const float*)d_in[7];  const float* Wih_b = (const float*)d_in[8];
    const float* Wfx_w = (const float*)d_in[9];  const float* Wfx_b = (const float*)d_in[10];
    const float* Wfh_w = (const float*)d_in[11]; const float* Wfh_b = (const float*)d_in[12];
    const float* Wox_w = (const float*)d_in[13]; const float* Wox_b = (const float*)d_in[14];
    const float* Woh_w = (const float*)d_in[15]; const float* Woh_b = (const float*)d_in[16];
    const float* Wph_w = (const float*)d_in[17]; const float* Wph_b = (const float*)d_in[18];
    const float* bg    = (const float*)d_in[19];
    const float* bi    = (const float*)d_in[20];
    const float* bf    = (const float*)d_in[21];
    const float* bo    = (const float*)d_in[22];
    const float* bp    = (const float*)d_in[23];
    float* out = (float*)d_out;

    static bool attr_done = false;
    if (!attr_done) {
        cudaFuncSetAttribute(scan_kernel, cudaFuncAttributeMaxDynamicSharedMemorySize, SCAN_SMEM);
        attr_done = true;
    }

    CvtWParams cw;
    cw.Wx[0] = Wgx_w; cw.Wx[1] = Wix_w; cw.Wx[2] = Wfx_w; cw.Wx[3] = Wox_w;
    cw.Wxb[0] = Wgx_b; cw.Wxb[1] = Wix_b; cw.Wxb[2] = Wfx_b; cw.Wxb[3] = Wox_b;
    cw.Whb[0] = Wgh_b; cw.Whb[1] = Wih_b; cw.Whb[2] = Wfh_b; cw.Whb[3] = Woh_b;

    P1MParams pm;
    pm.bgate[0] = bg; pm.bgate[1] = bi; pm.bgate[2] = bf; pm.bgate[3] = bo;

    ScanParams sp;
    sp.Wh[0] = Wgh_w; sp.Wh[1] = Wih_w; sp.Wh[2] = Wfh_w; sp.Wh[3] = Woh_w;

    init_kernel<<<(BB * HH + 255) / 256, 256>>>();
    convert_w<<<(NNBLK * 16 * 32 + 255) / 256, 256>>>(cw);
    convert_x<<<(NMBLK * 16 * 32) / 256, 256>>>(x);
    dim3 gmm(8, MROWS / 128);
    p1_mma<<<gmm, 256>>>(pm);
    scan_kernel<<<128, TSCAN, SCAN_SMEM>>>(sp);
    proj_softmax<<<BB, OO>>>(Wph_w, Wph_b, bp, out);
}

// round 17
// speedup vs baseline: 2.3210x; 1.2594x over previous
#include <cuda_runtime.h>
#include <cuda_bf16.h>
#include <math.h>
#include <stdint.h>

#define BB 256
#define SS 512
#define DD 256
#define HH 256
#define OO 128
#define NCOL 1024            // 4 gates * HH
#define ROWS_PER_CTA 16
#define JS 32
#define NGROUPS 16
#define TSCAN 512
#define MROWS (BB * SS)      // 131072
#define NMBLK (MROWS / 16)   // 8192
#define NNBLK (NCOL / 8)     // 128

// scan smem layout (bytes)
#define APK_H 0
#define APK_L 8192
#define PRE_OFF 16384
#define BPK_H 25088
#define BPK_L 90624
#define SCAN_SMEM 156160

// ---------- device scratch ----------
__device__ float g_XP[(size_t)SS * BB * NCOL];   // [s][b][n]
__device__ float g_H[BB * HH];                   // final hidden state only
__device__ unsigned g_barCnt[NGROUPS];
__device__ uint4 g_XA_h[(size_t)NMBLK * 16 * 32];   // A-frag packed x hi
__device__ uint4 g_XA_l[(size_t)NMBLK * 16 * 32];   // A-frag packed x lo
__device__ uint2 g_WB_h[(size_t)NNBLK * 16 * 32];   // B-frag packed Wx hi
__device__ uint2 g_WB_l[(size_t)NNBLK * 16 * 32];   // B-frag packed Wx lo
__device__ float g_bias[NCOL];                      // Wx_b + Wh_b per col
// h exchanged as pre-packed A-fragments (double buffered, per row-group)
__device__ uint4 g_HFh[2][NGROUPS][512];            // hi frags: 16ks*32ln*uint4
__device__ uint4 g_HFl[2][NGROUPS][512];            // lo frags

struct ScanParams { const float* Wh[4]; };
struct CvtWParams { const float* Wx[4]; const float* Wxb[4]; const float* Whb[4]; };
struct P1MParams  { const float* bgate[4]; };

// ---------- bf16 mma.sync helpers (verified R11/R12) ----------
__device__ __forceinline__ void mma16816(float c[4],
                                         uint32_t a0, uint32_t a1, uint32_t a2, uint32_t a3,
                                         uint32_t b0, uint32_t b1) {
    asm volatile(
        "mma.sync.aligned.m16n8k16.row.col.f32.bf16.bf16.f32 "
        "{%0,%1,%2,%3}, {%4,%5,%6,%7}, {%8,%9}, {%0,%1,%2,%3};"
        : "+f"(c[0]), "+f"(c[1]), "+f"(c[2]), "+f"(c[3])
        : "r"(a0), "r"(a1), "r"(a2), "r"(a3), "r"(b0), "r"(b1));
}
__device__ __forceinline__ uint32_t bfpair(float x, float y) {
    __nv_bfloat162 p;
    p.x = __float2bfloat16_rn(x);
    p.y = __float2bfloat16_rn(y);
    return *(uint32_t*)&p;
}
__device__ __forceinline__ float bfres(float x) {
    return x - __bfloat162float(__float2bfloat16_rn(x));
}
__device__ __forceinline__ float fast_sigmoid(float x) {
    return __fdividef(1.f, 1.f + __expf(-x));
}
__device__ __forceinline__ float fast_tanh(float x) {
    float e = __expf(fminf(x + x, 80.f));
    return __fdividef(e - 1.f, e + 1.f);
}

// ---------- init ----------
__global__ __launch_bounds__(256) void init_kernel() {
    unsigned i = blockIdx.x * blockDim.x + threadIdx.x;
    if (i < (unsigned)(BB * HH)) g_H[i] = 0.f;
    if (i < NGROUPS) g_barCnt[i] = 0u;
    if (i < (unsigned)(NGROUPS * 512)) {
        ((uint4*)g_HFh[0])[i] = make_uint4(0, 0, 0, 0);
        ((uint4*)g_HFl[0])[i] = make_uint4(0, 0, 0, 0);
    }
}

// ---------- convert x -> A-fragment-packed bf16 hi/lo ----------
__global__ __launch_bounds__(256) void convert_x(const float* __restrict__ x) {
    unsigned gid = blockIdx.x * 256u + threadIdx.x;
    int lane = gid & 31;
    int ks = (gid >> 5) & 15;
    int mblk = gid >> 9;
    int r = lane >> 2;
    int k0 = ks * 16 + (lane & 3) * 2;
    const float* xr  = x + (size_t)(mblk * 16 + r) * DD;
    const float* xr8 = xr + (size_t)8 * DD;
    float2 f0 = *(const float2*)&xr[k0];
    float2 f1 = *(const float2*)&xr8[k0];
    float2 f2 = *(const float2*)&xr[k0 + 8];
    float2 f3 = *(const float2*)&xr8[k0 + 8];
    uint4 hi, lo;
    hi.x = bfpair(f0.x, f0.y); lo.x = bfpair(bfres(f0.x), bfres(f0.y));
    hi.y = bfpair(f1.x, f1.y); lo.y = bfpair(bfres(f1.x), bfres(f1.y));
    hi.z = bfpair(f2.x, f2.y); lo.z = bfpair(bfres(f2.x), bfres(f2.y));
    hi.w = bfpair(f3.x, f3.y); lo.w = bfpair(bfres(f3.x), bfres(f3.y));
    size_t idx = ((size_t)mblk * 16 + ks) * 32 + lane;
    g_XA_h[idx] = hi;
    g_XA_l[idx] = lo;
}

// ---------- convert Wx -> B-fragment-packed bf16 hi/lo + fused bias ----------
__global__ __launch_bounds__(256) void convert_w(CvtWParams p) {
    unsigned gid = blockIdx.x * 256u + threadIdx.x;
    if (gid >= (unsigned)(NNBLK * 16 * 32)) return;
    int lane = gid & 31;
    int ks = (gid >> 5) & 15;
    int nblk = gid >> 9;
    int n = nblk * 8 + (lane >> 2);
    int g = n >> 8;
    int j = n & 255;
    int k0 = ks * 16 + (lane & 3) * 2;
    const float* wr = p.Wx[g] + (size_t)j * DD;
    float2 fa = *(const float2*)&wr[k0];
    float2 fb = *(const float2*)&wr[k0 + 8];
    uint2 hi, lo;
    hi.x = bfpair(fa.x, fa.y); lo.x = bfpair(bfres(fa.x), bfres(fa.y));
    hi.y = bfpair(fb.x, fb.y); lo.y = bfpair(bfres(fb.x), bfres(fb.y));
    size_t idx = ((size_t)nblk * 16 + ks) * 32 + lane;
    g_WB_h[idx] = hi;
    g_WB_l[idx] = lo;
    if (ks == 0 && (lane & 3) == 0)
        g_bias[n] = p.Wxb[g][j] + p.Whb[g][j];
}

// ---------- phase 1 GEMM on tensor cores (occupancy 2 via launch bounds) ----------
__global__ __launch_bounds__(256, 2) void p1_mma(P1MParams p) {
    const int tid = threadIdx.x;
    const int lane = tid & 31;
    const int warp = tid >> 5;
    const int wm = warp >> 1;
    const int wn = warp & 1;
    const int mblk0 = blockIdx.y * 8 + wm * 2;
    const int nblk0 = blockIdx.x * 16 + wn * 8;

    float c[2][8][4];
#pragma unroll
    for (int mb = 0; mb < 2; mb++)
#pragma unroll
        for (int nb = 0; nb < 8; nb++)
#pragma unroll
            for (int q = 0; q < 4; q++) c[mb][nb][q] = 0.f;

#pragma unroll
    for (int ks = 0; ks < 16; ks++) {
        uint4 ah0 = g_XA_h[((size_t)mblk0 * 16 + ks) * 32 + lane];
        uint4 ah1 = g_XA_h[((size_t)(mblk0 + 1) * 16 + ks) * 32 + lane];
        uint4 al0 = g_XA_l[((size_t)mblk0 * 16 + ks) * 32 + lane];
        uint4 al1 = g_XA_l[((size_t)(mblk0 + 1) * 16 + ks) * 32 + lane];
#pragma unroll
        for (int nb = 0; nb < 8; nb++) {
            size_t bidx = ((size_t)(nblk0 + nb) * 16 + ks) * 32 + lane;
            uint2 bh = g_WB_h[bidx];
            uint2 bl = g_WB_l[bidx];
            mma16816(c[0][nb], ah0.x, ah0.y, ah0.z, ah0.w, bh.x, bh.y);
            mma16816(c[0][nb], ah0.x, ah0.y, ah0.z, ah0.w, bl.x, bl.y);
            mma16816(c[0][nb], al0.x, al0.y, al0.z, al0.w, bh.x, bh.y);
            mma16816(c[1][nb], ah1.x, ah1.y, ah1.z, ah1.w, bh.x, bh.y);
            mma16816(c[1][nb], ah1.x, ah1.y, ah1.z, ah1.w, bl.x, bl.y);
            mma16816(c[1][nb], al1.x, al1.y, al1.z, al1.w, bh.x, bh.y);
        }
    }

    const int b = (int)(blockIdx.y >> 2);
#pragma unroll
    for (int nb = 0; nb < 8; nb++) {
        int n0 = nblk0 * 8 + nb * 8 + (lane & 3) * 2;
        int g = n0 >> 8;
        int j = n0 & 255;
        float2 bias;
        bias.x = g_bias[n0]     + __ldg(&p.bgate[g][(size_t)b * HH + j]);
        bias.y = g_bias[n0 + 1] + __ldg(&p.bgate[g][(size_t)b * HH + j + 1]);
#pragma unroll
        for (int mb = 0; mb < 2; mb++) {
            int mrow = blockIdx.y * 128 + wm * 32 + mb * 16 + (lane >> 2);
            int s0 = mrow & 511;
            int s1 = (mrow + 8) & 511;
            float2 o0 = make_float2(c[mb][nb][0] + bias.x, c[mb][nb][1] + bias.y);
            float2 o1 = make_float2(c[mb][nb][2] + bias.x, c[mb][nb][3] + bias.y);
            *(float2*)&g_XP[((size_t)s0 * BB + b) * NCOL + n0] = o0;
            *(float2*)&g_XP[((size_t)s1 * BB + b) * NCOL + n0] = o1;
        }
    }
}

// ---------- persistent recurrent scan: bf16-split HMMA, fragment h-exchange ----------
// h(t+1) is packed into A-fragment bf16 hi/lo words by the producing threads
// BEFORE the barrier; after the barrier each CTA does a coalesced 16KB copy
// gmem->smem and runs the (proven) mma mainloop. Gate math uses fast intrinsics.
__global__ __launch_bounds__(TSCAN, 1) void scan_kernel(ScanParams p) {
    extern __shared__ __align__(16) char smem[];
    uint32_t* apk_h = (uint32_t*)(smem + APK_H);
    uint32_t* apk_l = (uint32_t*)(smem + APK_L);
    float*    pre   = (float*)(smem + PRE_OFF);
    uint32_t* bpk_h = (uint32_t*)(smem + BPK_H);
    uint32_t* bpk_l = (uint32_t*)(smem + BPK_L);

    const int tid = threadIdx.x;
    const int cb = blockIdx.x & 7;
    const int rb = blockIdx.x >> 3;
    const int b0 = rb * ROWS_PER_CTA;
    const int j0 = cb * JS;
    const int lane = tid & 31;
    const int warp = tid >> 5;

    // one-time W pre-pack (proven mapping)
    for (int s = tid; s < 8192; s += TSCAN) {
        int nblk = s >> 9;
        int ks = (s >> 5) & 15;
        int ln = s & 31;
        int n = nblk * 8 + (ln >> 2);
        int g = n >> 5;
        int jjx = n & 31;
        int k0 = ks * 16 + (ln & 3) * 2;
        const float* wr = p.Wh[g] + (size_t)(j0 + jjx) * HH;
        float2 fa = *(const float2*)&wr[k0];
        float2 fb = *(const float2*)&wr[k0 + 8];
        bpk_h[s * 2]     = bfpair(fa.x, fa.y);
        bpk_h[s * 2 + 1] = bfpair(fb.x, fb.y);
        bpk_l[s * 2]     = bfpair(bfres(fa.x), bfres(fa.y));
        bpk_l[s * 2 + 1] = bfpair(bfres(fb.x), bfres(fb.y));
    }
    __syncthreads();

    const int row = tid >> 5;       // owned batch row
    const int jj = tid & 31;        // owned hidden unit
    float cv = 0.f;                 // cell state (register)

    // producer fragment-word address for (row, jj even): pair (jj, jj+1)
    const int kp = (j0 + jj) >> 1;
    const int pks = kp >> 3;
    const int pkq = kp & 7;
    const int pdl = (row & 7) * 4 + (pkq & 3);
    const int preg = (row >> 3) + ((pkq >> 2) << 1);
    const int pa32 = pks * 128 + pdl * 4 + preg;

    const uint32_t* bh_base = bpk_h + (size_t)warp * 16 * 64;
    const uint32_t* bl_base = bpk_l + (size_t)warp * 16 * 64;

    for (int t = 0; t < SS; t++) {
        // xp prefetch (DRAM, longest latency first)
        const float* xpr = g_XP + ((size_t)t * BB + b0 + row) * NCOL + j0 + jj;
        float xg = __ldcg(xpr);
        float xi = __ldcg(xpr + 256);
        float xf = __ldcg(xpr + 512);
        float xo = __ldcg(xpr + 768);

        // coalesced copy of pre-packed h fragments: gmem -> smem (16KB)
        {
            uint4 vh = __ldcg(&g_HFh[t & 1][rb][tid]);
            uint4 vl = __ldcg(&g_HFl[t & 1][rb][tid]);
            ((uint4*)apk_h)[tid] = vh;
            ((uint4*)apk_l)[tid] = vl;
        }
        __syncthreads();

        // mainloop: 16 ksteps x (Ah*Bh + Ah*Bl + Al*Bh)  (proven)
        float c[4] = {0.f, 0.f, 0.f, 0.f};
#pragma unroll
        for (int ks = 0; ks < 16; ks++) {
            uint4 ah = *(const uint4*)&apk_h[ks * 128 + lane * 4];
            uint2 bh = *(const uint2*)&bh_base[(ks * 32 + lane) * 2];
            mma16816(c, ah.x, ah.y, ah.z, ah.w, bh.x, bh.y);
            uint2 bl = *(const uint2*)&bl_base[(ks * 32 + lane) * 2];
            mma16816(c, ah.x, ah.y, ah.z, ah.w, bl.x, bl.y);
            uint4 al = *(const uint4*)&apk_l[ks * 128 + lane * 4];
            mma16816(c, al.x, al.y, al.z, al.w, bh.x, bh.y);
        }

        // stage D to smem
        {
            int r0 = lane >> 2;
            int n0 = warp * 8 + (lane & 3) * 2;
            pre[n0 * 17 + r0]           = c[0];
            pre[(n0 + 1) * 17 + r0]     = c[1];
            pre[n0 * 17 + r0 + 8]       = c[2];
            pre[(n0 + 1) * 17 + r0 + 8] = c[3];
        }
        __syncthreads();

        // gate math (fast intrinsics) + fragment pack + publish
        {
            float pg = pre[jj * 17 + row]         + xg;
            float pi = pre[(32 + jj) * 17 + row]  + xi;
            float pf = pre[(64 + jj) * 17 + row]  + xf;
            float po = pre[(96 + jj) * 17 + row]  + xo;
            float gv = fast_tanh(pg);
            float iv = fast_sigmoid(pi);
            float fv = fast_sigmoid(pf);
            float ov = fast_sigmoid(po);
            cv = fmaf(gv, iv, cv * fv);
            float hv = fast_tanh(cv) * ov;

            float hn = __shfl_down_sync(0xffffffffu, hv, 1);
            if ((jj & 1) == 0) {
                uint32_t* dsth = (uint32_t*)g_HFh[(t + 1) & 1][rb];
                uint32_t* dstl = (uint32_t*)g_HFl[(t + 1) & 1][rb];
                __stcg(&dsth[pa32], bfpair(hv, hn));
                __stcg(&dstl[pa32], bfpair(bfres(hv), bfres(hn)));
            }
            if (t == SS - 1)
                g_H[(size_t)(b0 + row) * HH + (j0 + jj)] = hv;
        }
        __syncthreads();

        // cross-CTA row-group barrier (monotone counter; proven)
        if (tid == 0) {
            __threadfence();
            unsigned old = atomicAdd(&g_barCnt[rb], 1u);
            unsigned target = 8u * (unsigned)(t + 1);
            if (old + 1u < target) {
                while (*(volatile unsigned*)&g_barCnt[rb] < target) { }
            }
            __threadfence();
        }
        __syncthreads();
    }
}

// ---------- final projection + softmax ----------
__global__ __launch_bounds__(128) void proj_softmax(const float* __restrict__ Wph,
                                                    const float* __restrict__ Wphb,
                                                    const float* __restrict__ bp,
                                                    float* __restrict__ out) {
    __shared__ float hsh[HH];
    __shared__ float red[OO];
    const int b = blockIdx.x;
    const int o = threadIdx.x;
    hsh[o]       = g_H[(size_t)b * HH + o];
    hsh[o + 128] = g_H[(size_t)b * HH + o + 128];
    __syncthreads();

    float acc = 0.f;
    const float* wr = Wph + (size_t)o * HH;
#pragma unroll 8
    for (int k = 0; k < HH; k += 4) {
        float4 w = *(const float4*)&wr[k];
        acc = fmaf(hsh[k],   w.x, acc);
        acc = fmaf(hsh[k+1], w.y, acc);
        acc = fmaf(hsh[k+2], w.z, acc);
        acc = fmaf(hsh[k+3], w.w, acc);
    }
    float pv = acc + Wphb[o] + bp[(size_t)b * OO + o];

    red[o] = pv;
    __syncthreads();
#pragma unroll
    for (int s = 64; s > 0; s >>= 1) {
        if (o < s) red[o] = fmaxf(red[o], red[o + s]);
        __syncthreads();
    }
    float mx = red[0];
    __syncthreads();
    float e = expf(pv - mx);
    red[o] = e;
    __syncthreads();
#pragma unroll
    for (int s = 64; s > 0; s >>= 1) {
        if (o < s) red[o] += red[o + s];
        __syncthreads();
    }
    out[(size_t)b * OO + o] = e / red[0];
}

// ---------- launch ----------
extern "C" void kernel_launch(void* const* d_in, const int* in_sizes, int n_in,
                              void* d_out, int out_size) {
    (void)in_sizes; (void)n_in; (void)out_size;
    const float* x     = (const float*)d_in[0];
    const float* Wgx_w = (const float*)d_in[1];  const float* Wgx_b = (const float*)d_in[2];
    const float* Wgh_w = (const float*)d_in[3];  const float* Wgh_b = (const float*)d_in[4];
    const float* Wix_w = (const float*)d_in[5];  const float* Wix_b = (const float*)d_in[6];
    const float* Wih_w = (const float*)d_in[7];  const float* Wih_b = (const float*)d_in[8];
    const float* Wfx_w = (const float*)d_in[9];  const float* Wfx_b = (const float*)d_in[10];
    const float* Wfh_w = (const float*)d_in[11]; const float* Wfh_b = (const float*)d_in[12];
    const float* Wox_w = (const float*)d_in[13]; const float* Wox_b = (const float*)d_in[14];
    const float* Woh_w = (const float*)d_in[15]; const float* Woh_b = (const float*)d_in[16];
    const float* Wph_w = (const float*)d_in[17]; const float* Wph_b = (const float*)d_in[18];
    const float* bg    = (const float*)d_in[19];
    const float* bi    = (const float*)d_in[20];
    const float* bf    = (const float*)d_in[21];
    const float* bo    = (const float*)d_in[22];
    const float* bp    = (const float*)d_in[23];
    float* out = (float*)d_out;

    static bool attr_done = false;
    if (!attr_done) {
        cudaFuncSetAttribute(scan_kernel, cudaFuncAttributeMaxDynamicSharedMemorySize, SCAN_SMEM);
        attr_done = true;
    }

    CvtWParams cw;
    cw.Wx[0] = Wgx_w; cw.Wx[1] = Wix_w; cw.Wx[2] = Wfx_w; cw.Wx[3] = Wox_w;
    cw.Wxb[0] = Wgx_b; cw.Wxb[1] = Wix_b; cw.Wxb[2] = Wfx_b; cw.Wxb[3] = Wox_b;
    cw.Whb[0] = Wgh_b; cw.Whb[1] = Wih_b; cw.Whb[2] = Wfh_b; cw.Whb[3] = Woh_b;

    P1MParams pm;
    pm.bgate[0] = bg; pm.bgate[1] = bi; pm.bgate[2] = bf; pm.bgate[3] = bo;

    ScanParams sp;
    sp.Wh[0] = Wgh_w; sp.Wh[1] = Wih_w; sp.Wh[2] = Wfh_w; sp.Wh[3] = Woh_w;

    init_kernel<<<(BB * HH + 255) / 256, 256>>>();
    convert_w<<<(NNBLK * 16 * 32 + 255) / 256, 256>>>(cw);
    convert_x<<<(NMBLK * 16 * 32) / 256, 256>>>(x);
    dim3 gmm(8, MROWS / 128);
    p1_mma<<<gmm, 256>>>(pm);
    scan_kernel<<<128, TSCAN, SCAN_SMEM>>>(sp);
    proj_softmax<<<BB, OO>>>(Wph_w, Wph_b, bp, out);
}